// round 13
// baseline (speedup 1.0000x reference)
#include <cuda_runtime.h>
#include <cuda_bf16.h>
#include <math.h>
#include <stdint.h>

#define Bc 4
#define Gc 2048
#define Dc 256
#define Hc 8
#define Lc 4
#define FFNc 1024
#define HDc 32
#define BGc (Bc*Gc)
#define NCc 32
#define Tc (Gc/NCc)   /* 64 */

// ---------------- scratch (no mallocs allowed) ----------------
__device__ float g_h[BGc*Dc];
__device__ float g_q[BGc*Dc];
__device__ float g_k[BGc*Dc];
__device__ float g_v[BGc*Dc];
__device__ float g_cKV[Bc*Hc*NCc*HDc*HDc];
__device__ float g_cK[Bc*Hc*NCc*HDc];

// packed bf16 hi/lo activations: [row][k2] k-contiguous
__device__ uint32_t g_zh[BGc*Dc/2];
__device__ uint32_t g_zl[BGc*Dc/2];
__device__ uint32_t g_uh[BGc*FFNc/2];
__device__ uint32_t g_ul[BGc*FFNc/2];
// packed bf16 hi/lo weights, TRANSPOSED: [layer][n][k2] k-contiguous
__device__ uint32_t g_Wqh[Lc*Dc*(Dc/2)];
__device__ uint32_t g_Wql[Lc*Dc*(Dc/2)];
__device__ uint32_t g_Wkh[Lc*Dc*(Dc/2)];
__device__ uint32_t g_Wkl[Lc*Dc*(Dc/2)];
__device__ uint32_t g_Wvh[Lc*Dc*(Dc/2)];
__device__ uint32_t g_Wvl[Lc*Dc*(Dc/2)];
__device__ uint32_t g_WUh[Lc*FFNc*(Dc/2)];
__device__ uint32_t g_WUl[Lc*FFNc*(Dc/2)];
__device__ uint32_t g_WVh[Lc*Dc*(FFNc/2)];
__device__ uint32_t g_WVl[Lc*Dc*(FFNc/2)];

// ---------------- helpers ----------------
__device__ __forceinline__ uint16_t bfb(float x){
    __nv_bfloat16 h = __float2bfloat16(x);
    return *reinterpret_cast<uint16_t*>(&h);
}
__device__ __forceinline__ float bff(uint16_t b){
    __nv_bfloat16 h = *reinterpret_cast<__nv_bfloat16*>(&b);
    return __bfloat162float(h);
}
__device__ __forceinline__ uint32_t pack2(uint16_t lo, uint16_t hi){
    return ((uint32_t)hi<<16) | (uint32_t)lo;
}
__device__ __forceinline__ void mma16816(float* c, const uint32_t* a, const uint32_t* b){
    asm volatile("mma.sync.aligned.m16n8k16.row.col.f32.bf16.bf16.f32 "
        "{%0,%1,%2,%3}, {%4,%5,%6,%7}, {%8,%9}, {%0,%1,%2,%3};\n"
        : "+f"(c[0]),"+f"(c[1]),"+f"(c[2]),"+f"(c[3])
        : "r"(a[0]),"r"(a[1]),"r"(a[2]),"r"(a[3]), "r"(b[0]),"r"(b[1]));
}
__device__ __forceinline__ void ldsm4(uint32_t* r, uint32_t addr){
    asm volatile("ldmatrix.sync.aligned.m8n8.x4.shared.b16 {%0,%1,%2,%3}, [%4];"
        : "=r"(r[0]),"=r"(r[1]),"=r"(r[2]),"=r"(r[3]) : "r"(addr));
}
__device__ __forceinline__ void cpa16(uint32_t s, const void* g){
    asm volatile("cp.async.cg.shared.global [%0], [%1], 16;" :: "r"(s), "l"(g));
}
#define CP_COMMIT() asm volatile("cp.async.commit_group;")
#define CP_WAIT0()  asm volatile("cp.async.wait_group 0;")

// ---------------- weight pack+transpose: W [L][K][N] -> Ph/Pl [L][N][K/2] ----------------
__global__ void packwT_kernel(const float* __restrict__ W, uint32_t* __restrict__ Ph,
                              uint32_t* __restrict__ Pl, int K, int N){
    __shared__ float tile[64][65];
    int k0 = blockIdx.x*64, n0 = blockIdx.y*64, l = blockIdx.z;
    const float* Wl = W + (size_t)l*K*N;
    int tid = threadIdx.x;
    #pragma unroll
    for (int i=0;i<16;i++){
        int idx = tid + i*256;
        int kk = idx>>6, nn = idx&63;
        tile[kk][nn] = Wl[(size_t)(k0+kk)*N + n0+nn];
    }
    __syncthreads();
    int Kp = K>>1;
    uint32_t* PhL = Ph + (size_t)l*N*Kp;
    uint32_t* PlL = Pl + (size_t)l*N*Kp;
    #pragma unroll
    for (int i=0;i<8;i++){
        int idx = tid + i*256;
        int nn = idx>>5, q = idx&31;
        float a = tile[q*2][nn], b = tile[q*2+1][nn];
        uint16_t ha=bfb(a), hb=bfb(b);
        size_t off = (size_t)(n0+nn)*Kp + (k0>>1) + q;
        PhL[off] = pack2(ha,hb);
        PlL[off] = pack2(bfb(a-bff(ha)), bfb(b-bff(hb)));
    }
}

// ---------------- embed ----------------
__global__ void embed_kernel(const float* __restrict__ x, const float* __restrict__ ge){
    int row = blockIdx.x;
    int d = threadIdx.x;
    int g = row % Gc;
    float xv = x[row];
    int i = (d < Dc/2) ? d : d - Dc/2;
    float invf = expf(-((2.0f*(float)i)/(float)Dc) * 4.6051701859880914f);
    float f = xv * invf;
    float ree = (d < Dc/2) ? sinf(f) : cosf(f);
    if (xv == -10.0f) ree = 0.0f;
    g_h[(size_t)row*Dc + d] = ge[(size_t)g*Dc + d] + ree;
}

// ---------------- layernorm: warp-per-row, packed hi/lo output ----------------
__global__ void ln_kernel(const float* __restrict__ in, const float* __restrict__ gamma,
                          const float* __restrict__ beta,
                          uint32_t* __restrict__ zh, uint32_t* __restrict__ zl){
    int row  = blockIdx.x*8 + (threadIdx.x >> 5);
    int lane = threadIdx.x & 31;
    const float2* p = (const float2*)(in + (size_t)row*Dc);
    float2 v[4]; float s = 0.f;
    #pragma unroll
    for (int j=0;j<4;j++){ v[j] = p[lane + j*32]; s += v[j].x + v[j].y; }
    #pragma unroll
    for (int o=16;o;o>>=1) s += __shfl_xor_sync(0xffffffffu, s, o);
    float mu = s * (1.0f/(float)Dc);
    float vs = 0.f;
    #pragma unroll
    for (int j=0;j<4;j++){
        float dx = v[j].x-mu, dy = v[j].y-mu;
        vs += dx*dx + dy*dy;
    }
    #pragma unroll
    for (int o=16;o;o>>=1) vs += __shfl_xor_sync(0xffffffffu, vs, o);
    float r = rsqrtf(vs*(1.0f/(float)Dc) + 1e-5f);
    const float2* gg = (const float2*)gamma;
    const float2* bb = (const float2*)beta;
    #pragma unroll
    for (int j=0;j<4;j++){
        int c2 = lane + j*32;
        float2 gv = gg[c2], bv = bb[c2];
        float a = (v[j].x-mu)*r*gv.x + bv.x;
        float b = (v[j].y-mu)*r*gv.y + bv.y;
        uint16_t ha = bfb(a), hb = bfb(b);
        zh[(size_t)row*(Dc/2) + c2] = pack2(ha,hb);
        zl[(size_t)row*(Dc/2) + c2] = pack2(bfb(a-bff(ha)), bfb(b-bff(hb)));
    }
}

// ---------------- bf16-split GEMM: 64x128 tile, 128 thr, cp.async 2-buf, ldmatrix frags ----------------
#define EPI_NONE   0
#define EPI_SQUARE 1
#define EPI_GELU   2

#define ASTR32 20
#define BSTRn  20
#define AU32   (64*ASTR32)        /* 1280 */
#define BU32n  (128*BSTRn)        /* 2560 */
#define BUFU32 (2*AU32 + 2*BU32n) /* 7680 u32 = 30720 B */
#define SMEM_GEMM (2*BUFU32*4)    /* 61440 B */

template<int EPI, bool RES, bool QKV, bool OUTPK>
__global__ void __launch_bounds__(128) mma_gemm(int M, int N, int K,
        const uint32_t* __restrict__ Agh, const uint32_t* __restrict__ Agl,
        const uint32_t* W0h, const uint32_t* W0l,
        const uint32_t* W1h, const uint32_t* W1l,
        const uint32_t* W2h, const uint32_t* W2l,
        const float* b0, const float* b1, const float* b2,
        float* C0, float* C1, float* C2,
        uint32_t* Coh, uint32_t* Col){
    extern __shared__ __align__(16) uint32_t smem[];

    const int z = QKV ? blockIdx.z : 0;
    const uint32_t* Bwh = QKV ? ((z==0)?W0h:((z==1)?W1h:W2h)) : W0h;
    const uint32_t* Bwl = QKV ? ((z==0)?W0l:((z==1)?W1l:W2l)) : W0l;
    const float* bias   = QKV ? ((z==0)?b0:((z==1)?b1:b2)) : b0;
    float*       C      = QKV ? ((z==0)?C0:((z==1)?C1:C2)) : C0;

    const int Kp = K/2;
    const int tid  = threadIdx.x;
    const int row0 = blockIdx.y*64;
    const int col0 = blockIdx.x*128;
    const int w    = tid>>5;
    const int wm   = w & 1;
    const int wn   = w >> 1;
    const int lane = tid & 31;
    const int g    = lane >> 2;
    const int t4   = lane & 3;

    // loader indices
    const int ar  = tid>>1, ac = (tid&1)*8;      // A: 64 rows, 2x16B each

    uint32_t sbase = (uint32_t)__cvta_generic_to_shared(smem);

    auto issue = [&](int bfr, int kt){
        int k0p = kt*16;
        uint32_t ah = sbase + (bfr*BUFU32)*4;
        uint32_t al = ah + AU32*4;
        uint32_t bh = al + AU32*4;
        uint32_t bl = bh + BU32n*4;
        const uint32_t* gAh = Agh + (size_t)(row0+ar)*Kp + k0p + ac;
        const uint32_t* gAl = Agl + (size_t)(row0+ar)*Kp + k0p + ac;
        uint32_t sA = (ar*ASTR32 + ac)*4;
        cpa16(ah + sA,      gAh);
        cpa16(ah + sA + 16, gAh + 4);
        cpa16(al + sA,      gAl);
        cpa16(al + sA + 16, gAl + 4);
        const uint32_t* gBh = Bwh + (size_t)(col0+tid)*Kp + k0p;
        const uint32_t* gBl = Bwl + (size_t)(col0+tid)*Kp + k0p;
        uint32_t sB = (tid*BSTRn)*4;
        #pragma unroll
        for (int c=0;c<4;c++){
            cpa16(bh + sB + c*16, gBh + c*4);
            cpa16(bl + sB + c*16, gBl + c*4);
        }
        CP_COMMIT();
    };

    float acc[2][8][4];
    #pragma unroll
    for (int mt=0;mt<2;mt++)
        #pragma unroll
        for (int nt=0;nt<8;nt++)
            #pragma unroll
            for (int q=0;q<4;q++) acc[mt][nt][q]=0.f;

    const int nk = K/32;
    issue(0, 0);

    // per-thread ldmatrix address components (lane-dependent, loop-invariant)
    const int arow = (lane&7) + ((lane>>3)&1)*8;
    const int akq0 = (lane>>4)*4;
    const int bn_  = ((lane>>4)&1)*8 + (lane&7);
    const int bkq0 = ((lane>>3)&1)*4;

    for (int kt=0; kt<nk; kt++){
        const int cur = kt & 1;
        CP_WAIT0();
        __syncthreads();
        if (kt+1 < nk) issue(cur^1, kt+1);

        const uint32_t AhA = sbase + (cur*BUFU32)*4;
        const uint32_t AlA = AhA + AU32*4;
        const uint32_t BhA = AlA + AU32*4;
        const uint32_t BlA = BhA + BU32n*4;

        #pragma unroll
        for (int ks=0;ks<2;ks++){
            uint32_t afh[2][4], afl[2][4];
            #pragma unroll
            for (int mt=0;mt<2;mt++){
                uint32_t off = ((wm*32 + mt*16 + arow)*ASTR32 + ks*8 + akq0)*4;
                ldsm4(afh[mt], AhA + off);
                ldsm4(afl[mt], AlA + off);
            }
            #pragma unroll
            for (int ntp=0;ntp<4;ntp++){
                uint32_t boff = ((wn*64 + ntp*16 + bn_)*BSTRn + ks*8 + bkq0)*4;
                uint32_t bhq[4], blq[4];
                ldsm4(bhq, BhA + boff);
                ldsm4(blq, BlA + boff);
                #pragma unroll
                for (int half=0; half<2; half++){
                    int nt = ntp*2 + half;
                    #pragma unroll
                    for (int mt=0;mt<2;mt++){
                        mma16816(acc[mt][nt], afh[mt], bhq + half*2);
                        mma16816(acc[mt][nt], afh[mt], blq + half*2);
                        mma16816(acc[mt][nt], afl[mt], bhq + half*2);
                    }
                }
            }
        }
        __syncthreads();
    }

    const int epi = QKV ? ((z==2) ? EPI_NONE : EPI_SQUARE) : EPI;
    #pragma unroll
    for (int mt=0;mt<2;mt++){
        #pragma unroll
        for (int nt=0;nt<8;nt++){
            int r = row0 + wm*32 + mt*16 + g;
            int n = col0 + wn*64 + nt*8 + t4*2;
            #pragma unroll
            for (int half=0; half<2; half++){
                int rr = r + half*8;
                float v0 = acc[mt][nt][half*2+0] + bias[n];
                float v1 = acc[mt][nt][half*2+1] + bias[n+1];
                if (epi == EPI_SQUARE){ v0=v0*v0; v1=v1*v1; }
                if (epi == EPI_GELU){
                    v0 = 0.5f*v0*(1.0f + erff(v0*0.70710678118654752f));
                    v1 = 0.5f*v1*(1.0f + erff(v1*0.70710678118654752f));
                }
                if (OUTPK){
                    uint16_t h0 = bfb(v0), h1 = bfb(v1);
                    Coh[(size_t)rr*(N/2) + (n>>1)] = pack2(h0,h1);
                    Col[(size_t)rr*(N/2) + (n>>1)] = pack2(bfb(v0-bff(h0)), bfb(v1-bff(h1)));
                } else {
                    size_t idx = (size_t)rr*N + n;
                    if (RES){ C[idx] += v0; C[idx+1] += v1; }
                    else    { C[idx]  = v0; C[idx+1]  = v1; }
                }
            }
        }
    }
}

// ---------------- attention scan (R7 verbatim) ----------------
__global__ void __launch_bounds__(256) scanA_kernel(){
    __shared__ float Ks[Tc][33];
    __shared__ float Vs[Tc][33];
    int bid = blockIdx.x;
    int c  = bid & (NCc-1);
    int bh = bid >> 5;
    int b  = bh >> 3;
    int hh = bh & 7;
    int tid = threadIdx.x;
    size_t base = ((size_t)(b*Gc + c*Tc))*Dc + hh*HDc;
    #pragma unroll
    for (int i=0;i<8;i++){
        int idx = tid + i*256;
        int s = idx >> 5, m = idx & 31;
        size_t gi = base + (size_t)s*Dc + m;
        Ks[s][m] = g_k[gi];
        Vs[s][m] = g_v[gi];
    }
    __syncthreads();
    int d  = tid >> 3;
    int mg = (tid & 7)*4;
    float a0=0.f,a1=0.f,a2=0.f,a3=0.f;
    #pragma unroll
    for (int s=0;s<Tc;s++){
        float vd = Vs[s][d];
        a0 += vd*Ks[s][mg+0]; a1 += vd*Ks[s][mg+1];
        a2 += vd*Ks[s][mg+2]; a3 += vd*Ks[s][mg+3];
    }
    float* o = &g_cKV[(size_t)bid*1024 + d*32 + mg];
    o[0]=a0; o[1]=a1; o[2]=a2; o[3]=a3;
    if (tid < 32){
        float ks = 0.f;
        #pragma unroll
        for (int s=0;s<Tc;s++) ks += Ks[s][tid];
        g_cK[bid*32 + tid] = ks;
    }
}

__global__ void scanB_kernel(){
    int bh  = blockIdx.x >> 3;
    int seg = blockIdx.x & 7;
    int t   = seg*128 + threadIdx.x;
    float run = 0.f;
    for (int c=0;c<NCc;c++){
        size_t idx = ((size_t)(bh*NCc + c))*1024 + t;
        float val = g_cKV[idx];
        g_cKV[idx] = run;
        run += val;
    }
    if (seg == 0 && threadIdx.x < 32){
        float run2 = 0.f;
        int m = threadIdx.x;
        for (int c=0;c<NCc;c++){
            int idx = (bh*NCc + c)*32 + m;
            float val = g_cK[idx];
            g_cK[idx] = run2;
            run2 += val;
        }
    }
}

__global__ void __launch_bounds__(256) scanC_kernel(){
    __shared__ float Qs[Tc][33];
    __shared__ float Ks[Tc][33];
    __shared__ float Vs[Tc][33];
    __shared__ float Ps[Tc][65];
    __shared__ float KVsm[32*33];
    __shared__ float kps[32];
    __shared__ float dens[Tc];
    int bid = blockIdx.x;
    int c  = bid & (NCc-1);
    int bh = bid >> 5;
    int b  = bh >> 3;
    int hh = bh & 7;
    int tid = threadIdx.x;
    size_t base = ((size_t)(b*Gc + c*Tc))*Dc + hh*HDc;
    #pragma unroll
    for (int i=0;i<8;i++){
        int idx = tid + i*256;
        int s = idx >> 5, m = idx & 31;
        size_t gi = base + (size_t)s*Dc + m;
        Qs[s][m] = g_q[gi];
        Ks[s][m] = g_k[gi];
        Vs[s][m] = g_v[gi];
    }
    #pragma unroll
    for (int i=0;i<4;i++){
        int idx = tid + i*256;
        int d = idx >> 5, m = idx & 31;
        KVsm[m*33 + d] = g_cKV[(size_t)bid*1024 + idx];
    }
    if (tid < 32) kps[tid] = g_cK[bid*32 + tid];
    __syncthreads();
    {
        int s = tid >> 2;
        int quad = tid & 3;
        float qreg[32];
        #pragma unroll
        for (int m=0;m<32;m++) qreg[m] = Qs[s][m];
        float rowsum = 0.f;
        #pragma unroll
        for (int j=0;j<16;j++){
            int t = quad + j*4;
            float dot = 0.f;
            #pragma unroll
            for (int m=0;m<32;m++) dot += qreg[m]*Ks[t][m];
            float pv = (t <= s) ? dot : 0.f;
            Ps[s][t] = pv;
            rowsum += pv;
        }
        rowsum += __shfl_xor_sync(0xffffffffu, rowsum, 1);
        rowsum += __shfl_xor_sync(0xffffffffu, rowsum, 2);
        if (quad == 0) dens[s] = rowsum;
    }
    __syncthreads();
    if (tid < Tc){
        float den = dens[tid];
        #pragma unroll
        for (int m=0;m<32;m++) den += Qs[tid][m]*kps[m];
        dens[tid] = den + 1e-16f;
    }
    __syncthreads();
    #pragma unroll
    for (int i=0;i<8;i++){
        int idx = tid + i*256;
        int s = idx >> 5, d = idx & 31;
        float num = 0.f;
        #pragma unroll
        for (int t=0;t<Tc;t++) num += Ps[s][t]*Vs[t][d];
        #pragma unroll
        for (int m=0;m<32;m++) num += Qs[s][m]*KVsm[m*33 + d];
        g_h[base + (size_t)s*Dc + d] += num / dens[s];
    }
}

// ---------------- head ----------------
__global__ void out_kernel(const float* __restrict__ Wo, const float* __restrict__ bo,
                           float* __restrict__ out){
    int row  = blockIdx.x*8 + (threadIdx.x >> 5);
    int lane = threadIdx.x & 31;
    float s = 0.f;
    #pragma unroll
    for (int j=0;j<8;j++){
        int d = lane + j*32;
        s += g_h[(size_t)row*Dc + d] * Wo[d];
    }
    #pragma unroll
    for (int o=16;o;o>>=1) s += __shfl_xor_sync(0xffffffffu, s, o);
    if (lane == 0) out[row] = s + bo[0];
}

// ---------------- launch ----------------
extern "C" void kernel_launch(void* const* d_in, const int* in_sizes, int n_in,
                              void* d_out, int out_size){
    const float* x    = (const float*)d_in[0];
    const float* ge   = (const float*)d_in[1];
    const float* Wq   = (const float*)d_in[2];
    const float* bq   = (const float*)d_in[3];
    const float* Wk   = (const float*)d_in[4];
    const float* bk   = (const float*)d_in[5];
    const float* Wv   = (const float*)d_in[6];
    const float* bv   = (const float*)d_in[7];
    const float* ln1g = (const float*)d_in[8];
    const float* ln1b = (const float*)d_in[9];
    const float* ln2g = (const float*)d_in[10];
    const float* ln2b = (const float*)d_in[11];
    const float* WU   = (const float*)d_in[12];
    const float* bU   = (const float*)d_in[13];
    const float* WV   = (const float*)d_in[14];
    const float* bV   = (const float*)d_in[15];
    const float* Wo   = (const float*)d_in[16];
    const float* bo   = (const float*)d_in[17];
    float* out = (float*)d_out;

    float *ph, *pq, *pk, *pv;
    uint32_t *pzh, *pzl, *puh, *pul;
    uint32_t *pWqh,*pWql,*pWkh,*pWkl,*pWvh,*pWvl,*pWUh,*pWUl,*pWVh,*pWVl;
    cudaGetSymbolAddress((void**)&ph, g_h);
    cudaGetSymbolAddress((void**)&pq, g_q);
    cudaGetSymbolAddress((void**)&pk, g_k);
    cudaGetSymbolAddress((void**)&pv, g_v);
    cudaGetSymbolAddress((void**)&pzh, g_zh);
    cudaGetSymbolAddress((void**)&pzl, g_zl);
    cudaGetSymbolAddress((void**)&puh, g_uh);
    cudaGetSymbolAddress((void**)&pul, g_ul);
    cudaGetSymbolAddress((void**)&pWqh, g_Wqh);
    cudaGetSymbolAddress((void**)&pWql, g_Wql);
    cudaGetSymbolAddress((void**)&pWkh, g_Wkh);
    cudaGetSymbolAddress((void**)&pWkl, g_Wkl);
    cudaGetSymbolAddress((void**)&pWvh, g_Wvh);
    cudaGetSymbolAddress((void**)&pWvl, g_Wvl);
    cudaGetSymbolAddress((void**)&pWUh, g_WUh);
    cudaGetSymbolAddress((void**)&pWUl, g_WUl);
    cudaGetSymbolAddress((void**)&pWVh, g_WVh);
    cudaGetSymbolAddress((void**)&pWVl, g_WVl);

    cudaFuncSetAttribute(mma_gemm<EPI_NONE,false,true,false>,
        cudaFuncAttributeMaxDynamicSharedMemorySize, SMEM_GEMM);
    cudaFuncSetAttribute(mma_gemm<EPI_GELU,false,false,true>,
        cudaFuncAttributeMaxDynamicSharedMemorySize, SMEM_GEMM);
    cudaFuncSetAttribute(mma_gemm<EPI_NONE,true,false,false>,
        cudaFuncAttributeMaxDynamicSharedMemorySize, SMEM_GEMM);

    // pack+transpose all weights once per call
    packwT_kernel<<<dim3(Dc/64,   Dc/64,   Lc), 256>>>(Wq, pWqh, pWql, Dc,   Dc);
    packwT_kernel<<<dim3(Dc/64,   Dc/64,   Lc), 256>>>(Wk, pWkh, pWkl, Dc,   Dc);
    packwT_kernel<<<dim3(Dc/64,   Dc/64,   Lc), 256>>>(Wv, pWvh, pWvl, Dc,   Dc);
    packwT_kernel<<<dim3(Dc/64,   FFNc/64, Lc), 256>>>(WU, pWUh, pWUl, Dc,   FFNc);
    packwT_kernel<<<dim3(FFNc/64, Dc/64,   Lc), 256>>>(WV, pWVh, pWVl, FFNc, Dc);

    embed_kernel<<<BGc, Dc>>>(x, ge);

    const size_t wqkv = (size_t)Dc*(Dc/2);
    const size_t wu   = (size_t)FFNc*(Dc/2);
    const size_t wv2  = (size_t)Dc*(FFNc/2);

    for (int l=0;l<Lc;l++){
        ln_kernel<<<BGc/8, 256>>>(ph, ln1g + l*Dc, ln1b + l*Dc, pzh, pzl);
        dim3 gqkv(Dc/128, BGc/64, 3);
        mma_gemm<EPI_NONE,false,true,false><<<gqkv,128,SMEM_GEMM>>>(BGc, Dc, Dc, pzh, pzl,
            pWqh + l*wqkv, pWql + l*wqkv,
            pWkh + l*wqkv, pWkl + l*wqkv,
            pWvh + l*wqkv, pWvl + l*wqkv,
            bq + l*Dc, bk + l*Dc, bv + l*Dc,
            pq, pk, pv, 0, 0);
        scanA_kernel<<<Bc*Hc*NCc, 256>>>();
        scanB_kernel<<<Bc*Hc*8, 128>>>();
        scanC_kernel<<<Bc*Hc*NCc, 256>>>();

        ln_kernel<<<BGc/8, 256>>>(ph, ln2g + l*Dc, ln2b + l*Dc, pzh, pzl);
        dim3 gu(FFNc/128, BGc/64, 1);
        mma_gemm<EPI_GELU,false,false,true><<<gu,128,SMEM_GEMM>>>(BGc, FFNc, Dc, pzh, pzl,
            pWUh + l*wu, pWUl + l*wu, 0,0,0,0,
            bU + l*FFNc, 0, 0,
            0, 0, 0, puh, pul);
        dim3 gv(Dc/128, BGc/64, 1);
        mma_gemm<EPI_NONE,true,false,false><<<gv,128,SMEM_GEMM>>>(BGc, Dc, FFNc, puh, pul,
            pWVh + l*wv2, pWVl + l*wv2, 0,0,0,0,
            bV + l*Dc, 0, 0,
            ph, 0, 0, 0, 0);
    }

    out_kernel<<<BGc/8, 256>>>(Wo, bo, out);
}

// round 14
// speedup vs baseline: 1.7709x; 1.7709x over previous
#include <cuda_runtime.h>
#include <cuda_bf16.h>
#include <math.h>
#include <stdint.h>

#define Bc 4
#define Gc 2048
#define Dc 256
#define Hc 8
#define Lc 4
#define FFNc 1024
#define HDc 32
#define BGc (Bc*Gc)
#define NCc 32
#define Tc (Gc/NCc)   /* 64 */

// ---------------- scratch (no mallocs allowed) ----------------
__device__ float g_h[BGc*Dc];
__device__ float g_q[BGc*Dc];
__device__ float g_k[BGc*Dc];
__device__ float g_v[BGc*Dc];
__device__ float g_cKV[Bc*Hc*NCc*HDc*HDc];
__device__ float g_cK[Bc*Hc*NCc*HDc];

// packed bf16 hi/lo activations
__device__ uint32_t g_zh[BGc*Dc/2];
__device__ uint32_t g_zl[BGc*Dc/2];
__device__ uint32_t g_uh[BGc*FFNc/2];
__device__ uint32_t g_ul[BGc*FFNc/2];
// packed bf16 hi/lo weights (k2-major rows, n columns — R7 layout)
__device__ uint32_t g_Wqh[Lc*(Dc/2)*Dc];
__device__ uint32_t g_Wql[Lc*(Dc/2)*Dc];
__device__ uint32_t g_Wkh[Lc*(Dc/2)*Dc];
__device__ uint32_t g_Wkl[Lc*(Dc/2)*Dc];
__device__ uint32_t g_Wvh[Lc*(Dc/2)*Dc];
__device__ uint32_t g_Wvl[Lc*(Dc/2)*Dc];
__device__ uint32_t g_WUh[Lc*(Dc/2)*FFNc];
__device__ uint32_t g_WUl[Lc*(Dc/2)*FFNc];
__device__ uint32_t g_WVh[Lc*(FFNc/2)*Dc];
__device__ uint32_t g_WVl[Lc*(FFNc/2)*Dc];

// ---------------- helpers ----------------
__device__ __forceinline__ uint16_t bfb(float x){
    __nv_bfloat16 h = __float2bfloat16(x);
    return *reinterpret_cast<uint16_t*>(&h);
}
__device__ __forceinline__ float bff(uint16_t b){
    __nv_bfloat16 h = *reinterpret_cast<__nv_bfloat16*>(&b);
    return __bfloat162float(h);
}
__device__ __forceinline__ uint32_t pack2(uint16_t lo, uint16_t hi){
    return ((uint32_t)hi<<16) | (uint32_t)lo;
}
__device__ __forceinline__ void mma16816(float* c, const uint32_t* a, const uint32_t* b){
    asm volatile("mma.sync.aligned.m16n8k16.row.col.f32.bf16.bf16.f32 "
        "{%0,%1,%2,%3}, {%4,%5,%6,%7}, {%8,%9}, {%0,%1,%2,%3};\n"
        : "+f"(c[0]),"+f"(c[1]),"+f"(c[2]),"+f"(c[3])
        : "r"(a[0]),"r"(a[1]),"r"(a[2]),"r"(a[3]), "r"(b[0]),"r"(b[1]));
}
__device__ __forceinline__ void cpa16(uint32_t s, const void* g){
    asm volatile("cp.async.cg.shared.global [%0], [%1], 16;" :: "r"(s), "l"(g));
}
#define CP_COMMIT() asm volatile("cp.async.commit_group;")
#define CP_WAIT0()  asm volatile("cp.async.wait_group 0;")

// ---------------- merged weight packer: all 5 tensors in ONE launch ----------------
// Each thread produces one u32 of Ph/Pl. Layout identical to R7's packw output:
// [L*K/2 rows][N], u32 row r packs W[2r][n], W[2r+1][n].
#define S1c  (Lc*(Dc/2)*Dc)     /* 131072 */
#define SUc  (Lc*(Dc/2)*FFNc)   /* 524288 */
#define SVc  (Lc*(FFNc/2)*Dc)   /* 524288 */
#define PACK_TOTAL (3*S1c + SUc + SVc)  /* 1441792 */

__global__ void packAll_kernel(const float* __restrict__ Wq, const float* __restrict__ Wk,
                               const float* __restrict__ Wv, const float* __restrict__ WU,
                               const float* __restrict__ WV){
    int t = blockIdx.x*256 + threadIdx.x;
    const float* W; uint32_t *Ph, *Pl; int N, r;
    if (t < 3*S1c){
        int which = t / S1c; r = t - which*S1c;
        W  = (which==0)?Wq:((which==1)?Wk:Wv);
        Ph = (which==0)?g_Wqh:((which==1)?g_Wkh:g_Wvh);
        Pl = (which==0)?g_Wql:((which==1)?g_Wkl:g_Wvl);
        N = Dc;
    } else if (t < 3*S1c + SUc){
        r = t - 3*S1c; W = WU; Ph = g_WUh; Pl = g_WUl; N = FFNc;
    } else {
        r = t - 3*S1c - SUc; W = WV; Ph = g_WVh; Pl = g_WVl; N = Dc;
    }
    int row = r / N, n = r - row*N;
    float a = W[(size_t)(2*row)*N + n];
    float b = W[(size_t)(2*row+1)*N + n];
    uint16_t ha = bfb(a), hb = bfb(b);
    Ph[(size_t)row*N + n] = pack2(ha,hb);
    Pl[(size_t)row*N + n] = pack2(bfb(a-bff(ha)), bfb(b-bff(hb)));
}

// ---------------- embed ----------------
__global__ void embed_kernel(const float* __restrict__ x, const float* __restrict__ ge){
    int row = blockIdx.x;
    int d = threadIdx.x;
    int g = row % Gc;
    float xv = x[row];
    int i = (d < Dc/2) ? d : d - Dc/2;
    float invf = expf(-((2.0f*(float)i)/(float)Dc) * 4.6051701859880914f);
    float f = xv * invf;
    float ree = (d < Dc/2) ? sinf(f) : cosf(f);
    if (xv == -10.0f) ree = 0.0f;
    g_h[(size_t)row*Dc + d] = ge[(size_t)g*Dc + d] + ree;
}

// ---------------- layernorm: warp-per-row, packed hi/lo output ----------------
__global__ void ln_kernel(const float* __restrict__ in, const float* __restrict__ gamma,
                          const float* __restrict__ beta,
                          uint32_t* __restrict__ zh, uint32_t* __restrict__ zl){
    int row  = blockIdx.x*8 + (threadIdx.x >> 5);
    int lane = threadIdx.x & 31;
    const float2* p = (const float2*)(in + (size_t)row*Dc);
    float2 v[4]; float s = 0.f;
    #pragma unroll
    for (int j=0;j<4;j++){ v[j] = p[lane + j*32]; s += v[j].x + v[j].y; }
    #pragma unroll
    for (int o=16;o;o>>=1) s += __shfl_xor_sync(0xffffffffu, s, o);
    float mu = s * (1.0f/(float)Dc);
    float vs = 0.f;
    #pragma unroll
    for (int j=0;j<4;j++){
        float dx = v[j].x-mu, dy = v[j].y-mu;
        vs += dx*dx + dy*dy;
    }
    #pragma unroll
    for (int o=16;o;o>>=1) vs += __shfl_xor_sync(0xffffffffu, vs, o);
    float r = rsqrtf(vs*(1.0f/(float)Dc) + 1e-5f);
    const float2* gg = (const float2*)gamma;
    const float2* bb = (const float2*)beta;
    #pragma unroll
    for (int j=0;j<4;j++){
        int c2 = lane + j*32;
        float2 gv = gg[c2], bv = bb[c2];
        float a = (v[j].x-mu)*r*gv.x + bv.x;
        float b = (v[j].y-mu)*r*gv.y + bv.y;
        uint16_t ha = bfb(a), hb = bfb(b);
        zh[(size_t)row*(Dc/2) + c2] = pack2(ha,hb);
        zl[(size_t)row*(Dc/2) + c2] = pack2(bfb(a-bff(ha)), bfb(b-bff(hb)));
    }
}

// ---------------- bf16 split tensor-core GEMM, 64x128 tile, 128 thr, cp.async 2-buf ----------------
#define EPI_NONE   0
#define EPI_SQUARE 1
#define EPI_GELU   2

#define ASTR32 20
#define BSTR32 136
#define AU32   (64*ASTR32)      /* 1280 */
#define BU32   (16*BSTR32)      /* 2176 */
#define BUFU32 (2*AU32 + 2*BU32) /* 6912 u32 = 27648 B */
#define SMEM_GEMM (2*BUFU32*4)   /* 55296 B */

template<int EPI, bool RES, bool QKV, bool OUTPK>
__global__ void __launch_bounds__(128) mma_gemm(int M, int N, int K,
        const uint32_t* __restrict__ Agh, const uint32_t* __restrict__ Agl,
        const uint32_t* W0h, const uint32_t* W0l,
        const uint32_t* W1h, const uint32_t* W1l,
        const uint32_t* W2h, const uint32_t* W2l,
        const float* b0, const float* b1, const float* b2,
        float* C0, float* C1, float* C2,
        uint32_t* Coh, uint32_t* Col){
    extern __shared__ __align__(16) uint32_t smem[];

    const int z = QKV ? blockIdx.z : 0;
    const uint32_t* Bwh = QKV ? ((z==0)?W0h:((z==1)?W1h:W2h)) : W0h;
    const uint32_t* Bwl = QKV ? ((z==0)?W0l:((z==1)?W1l:W2l)) : W0l;
    const float* bias   = QKV ? ((z==0)?b0:((z==1)?b1:b2)) : b0;
    float*       C      = QKV ? ((z==0)?C0:((z==1)?C1:C2)) : C0;

    const int Kp = K/2;
    const int tid  = threadIdx.x;
    const int row0 = blockIdx.y*64;
    const int col0 = blockIdx.x*128;
    const int w    = tid>>5;
    const int wm   = w & 1;
    const int wn   = w >> 1;
    const int lane = tid & 31;
    const int g    = lane >> 2;
    const int t4   = lane & 3;

    // loader indices
    const int ar  = tid>>1, ac = (tid&1)*8;      // A: 64 rows x 16 u32
    const int bk2 = tid>>4, bn = (tid&15)*8;     // B: rows bk2, bk2+8

    uint32_t sbase = (uint32_t)__cvta_generic_to_shared(smem);

    auto issue = [&](int bfr, int kt){
        int k0p = kt*16;
        uint32_t ah = sbase + (bfr*BUFU32)*4;
        uint32_t al = ah + AU32*4;
        uint32_t bh = al + AU32*4;
        uint32_t bl = bh + BU32*4;
        const uint32_t* gAh = Agh + (size_t)(row0+ar)*Kp + k0p + ac;
        const uint32_t* gAl = Agl + (size_t)(row0+ar)*Kp + k0p + ac;
        uint32_t sA = (ar*ASTR32 + ac)*4;
        cpa16(ah + sA,      gAh);
        cpa16(ah + sA + 16, gAh + 4);
        cpa16(al + sA,      gAl);
        cpa16(al + sA + 16, gAl + 4);
        #pragma unroll
        for (int i=0;i<2;i++){
            int rb = bk2 + 8*i;
            const uint32_t* gBh = Bwh + (size_t)(k0p+rb)*N + col0 + bn;
            const uint32_t* gBl = Bwl + (size_t)(k0p+rb)*N + col0 + bn;
            uint32_t sB = (rb*BSTR32 + bn)*4;
            cpa16(bh + sB,      gBh);
            cpa16(bh + sB + 16, gBh + 4);
            cpa16(bl + sB,      gBl);
            cpa16(bl + sB + 16, gBl + 4);
        }
        CP_COMMIT();
    };

    float acc[2][8][4];
    #pragma unroll
    for (int mt=0;mt<2;mt++)
        #pragma unroll
        for (int nt=0;nt<8;nt++)
            #pragma unroll
            for (int q=0;q<4;q++) acc[mt][nt][q]=0.f;

    const int nk = K/32;
    issue(0, 0);

    for (int kt=0; kt<nk; kt++){
        const int cur = kt & 1;
        CP_WAIT0();
        __syncthreads();
        if (kt+1 < nk) issue(cur^1, kt+1);

        const uint32_t* AhS = smem + cur*BUFU32;
        const uint32_t* AlS = AhS + AU32;
        const uint32_t* BhS = AlS + AU32;
        const uint32_t* BlS = BhS + BU32;

        #pragma unroll
        for (int ks=0;ks<2;ks++){
            uint32_t afh[2][4], afl[2][4];
            #pragma unroll
            for (int mt=0;mt<2;mt++){
                int r  = wm*32 + mt*16 + g;
                int cb = ks*8 + t4;
                afh[mt][0]=AhS[r*ASTR32+cb];
                afh[mt][1]=AhS[(r+8)*ASTR32+cb];
                afh[mt][2]=AhS[r*ASTR32+cb+4];
                afh[mt][3]=AhS[(r+8)*ASTR32+cb+4];
                afl[mt][0]=AlS[r*ASTR32+cb];
                afl[mt][1]=AlS[(r+8)*ASTR32+cb];
                afl[mt][2]=AlS[r*ASTR32+cb+4];
                afl[mt][3]=AlS[(r+8)*ASTR32+cb+4];
            }
            #pragma unroll
            for (int nt=0;nt<8;nt++){
                int n  = wn*64 + nt*8 + g;
                int k2 = ks*8 + t4;
                uint32_t bhv[2], blv[2];
                bhv[0]=BhS[k2*BSTR32+n]; bhv[1]=BhS[(k2+4)*BSTR32+n];
                blv[0]=BlS[k2*BSTR32+n]; blv[1]=BlS[(k2+4)*BSTR32+n];
                // distance-2 same-accumulator spacing (vs 3 consecutive in R7)
                mma16816(acc[0][nt], afh[0], bhv);
                mma16816(acc[1][nt], afh[1], bhv);
                mma16816(acc[0][nt], afh[0], blv);
                mma16816(acc[1][nt], afh[1], blv);
                mma16816(acc[0][nt], afl[0], bhv);
                mma16816(acc[1][nt], afl[1], bhv);
            }
        }
        __syncthreads();
    }

    const int epi = QKV ? ((z==2) ? EPI_NONE : EPI_SQUARE) : EPI;
    #pragma unroll
    for (int mt=0;mt<2;mt++){
        #pragma unroll
        for (int nt=0;nt<8;nt++){
            int r = row0 + wm*32 + mt*16 + g;
            int n = col0 + wn*64 + nt*8 + t4*2;
            #pragma unroll
            for (int half=0; half<2; half++){
                int rr = r + half*8;
                float v0 = acc[mt][nt][half*2+0] + bias[n];
                float v1 = acc[mt][nt][half*2+1] + bias[n+1];
                if (epi == EPI_SQUARE){ v0=v0*v0; v1=v1*v1; }
                if (epi == EPI_GELU){
                    v0 = 0.5f*v0*(1.0f + erff(v0*0.70710678118654752f));
                    v1 = 0.5f*v1*(1.0f + erff(v1*0.70710678118654752f));
                }
                if (OUTPK){
                    uint16_t h0 = bfb(v0), h1 = bfb(v1);
                    Coh[(size_t)rr*(N/2) + (n>>1)] = pack2(h0,h1);
                    Col[(size_t)rr*(N/2) + (n>>1)] = pack2(bfb(v0-bff(h0)), bfb(v1-bff(h1)));
                } else {
                    size_t idx = (size_t)rr*N + n;
                    if (RES){ C[idx] += v0; C[idx+1] += v1; }
                    else    { C[idx]  = v0; C[idx+1]  = v1; }
                }
            }
        }
    }
}

// ---------------- attention scan (R7 verbatim) ----------------
__global__ void __launch_bounds__(256) scanA_kernel(){
    __shared__ float Ks[Tc][33];
    __shared__ float Vs[Tc][33];
    int bid = blockIdx.x;
    int c  = bid & (NCc-1);
    int bh = bid >> 5;
    int b  = bh >> 3;
    int hh = bh & 7;
    int tid = threadIdx.x;
    size_t base = ((size_t)(b*Gc + c*Tc))*Dc + hh*HDc;
    #pragma unroll
    for (int i=0;i<8;i++){
        int idx = tid + i*256;
        int s = idx >> 5, m = idx & 31;
        size_t gi = base + (size_t)s*Dc + m;
        Ks[s][m] = g_k[gi];
        Vs[s][m] = g_v[gi];
    }
    __syncthreads();
    int d  = tid >> 3;
    int mg = (tid & 7)*4;
    float a0=0.f,a1=0.f,a2=0.f,a3=0.f;
    #pragma unroll
    for (int s=0;s<Tc;s++){
        float vd = Vs[s][d];
        a0 += vd*Ks[s][mg+0]; a1 += vd*Ks[s][mg+1];
        a2 += vd*Ks[s][mg+2]; a3 += vd*Ks[s][mg+3];
    }
    float* o = &g_cKV[(size_t)bid*1024 + d*32 + mg];
    o[0]=a0; o[1]=a1; o[2]=a2; o[3]=a3;
    if (tid < 32){
        float ks = 0.f;
        #pragma unroll
        for (int s=0;s<Tc;s++) ks += Ks[s][tid];
        g_cK[bid*32 + tid] = ks;
    }
}

__global__ void scanB_kernel(){
    int bh  = blockIdx.x >> 3;
    int seg = blockIdx.x & 7;
    int t   = seg*128 + threadIdx.x;
    float run = 0.f;
    for (int c=0;c<NCc;c++){
        size_t idx = ((size_t)(bh*NCc + c))*1024 + t;
        float val = g_cKV[idx];
        g_cKV[idx] = run;
        run += val;
    }
    if (seg == 0 && threadIdx.x < 32){
        float run2 = 0.f;
        int m = threadIdx.x;
        for (int c=0;c<NCc;c++){
            int idx = (bh*NCc + c)*32 + m;
            float val = g_cK[idx];
            g_cK[idx] = run2;
            run2 += val;
        }
    }
}

__global__ void __launch_bounds__(256) scanC_kernel(){
    __shared__ float Qs[Tc][33];
    __shared__ float Ks[Tc][33];
    __shared__ float Vs[Tc][33];
    __shared__ float Ps[Tc][65];
    __shared__ float KVsm[32*33];
    __shared__ float kps[32];
    __shared__ float dens[Tc];
    int bid = blockIdx.x;
    int c  = bid & (NCc-1);
    int bh = bid >> 5;
    int b  = bh >> 3;
    int hh = bh & 7;
    int tid = threadIdx.x;
    size_t base = ((size_t)(b*Gc + c*Tc))*Dc + hh*HDc;
    #pragma unroll
    for (int i=0;i<8;i++){
        int idx = tid + i*256;
        int s = idx >> 5, m = idx & 31;
        size_t gi = base + (size_t)s*Dc + m;
        Qs[s][m] = g_q[gi];
        Ks[s][m] = g_k[gi];
        Vs[s][m] = g_v[gi];
    }
    #pragma unroll
    for (int i=0;i<4;i++){
        int idx = tid + i*256;
        int d = idx >> 5, m = idx & 31;
        KVsm[m*33 + d] = g_cKV[(size_t)bid*1024 + idx];
    }
    if (tid < 32) kps[tid] = g_cK[bid*32 + tid];
    __syncthreads();
    {
        int s = tid >> 2;
        int quad = tid & 3;
        float qreg[32];
        #pragma unroll
        for (int m=0;m<32;m++) qreg[m] = Qs[s][m];
        float rowsum = 0.f;
        #pragma unroll
        for (int j=0;j<16;j++){
            int t = quad + j*4;
            float dot = 0.f;
            #pragma unroll
            for (int m=0;m<32;m++) dot += qreg[m]*Ks[t][m];
            float pv = (t <= s) ? dot : 0.f;
            Ps[s][t] = pv;
            rowsum += pv;
        }
        rowsum += __shfl_xor_sync(0xffffffffu, rowsum, 1);
        rowsum += __shfl_xor_sync(0xffffffffu, rowsum, 2);
        if (quad == 0) dens[s] = rowsum;
    }
    __syncthreads();
    if (tid < Tc){
        float den = dens[tid];
        #pragma unroll
        for (int m=0;m<32;m++) den += Qs[tid][m]*kps[m];
        dens[tid] = den + 1e-16f;
    }
    __syncthreads();
    #pragma unroll
    for (int i=0;i<8;i++){
        int idx = tid + i*256;
        int s = idx >> 5, d = idx & 31;
        float num = 0.f;
        #pragma unroll
        for (int t=0;t<Tc;t++) num += Ps[s][t]*Vs[t][d];
        #pragma unroll
        for (int m=0;m<32;m++) num += Qs[s][m]*KVsm[m*33 + d];
        g_h[base + (size_t)s*Dc + d] += num / dens[s];
    }
}

// ---------------- head ----------------
__global__ void out_kernel(const float* __restrict__ Wo, const float* __restrict__ bo,
                           float* __restrict__ out){
    int row  = blockIdx.x*8 + (threadIdx.x >> 5);
    int lane = threadIdx.x & 31;
    float s = 0.f;
    #pragma unroll
    for (int j=0;j<8;j++){
        int d = lane + j*32;
        s += g_h[(size_t)row*Dc + d] * Wo[d];
    }
    #pragma unroll
    for (int o=16;o;o>>=1) s += __shfl_xor_sync(0xffffffffu, s, o);
    if (lane == 0) out[row] = s + bo[0];
}

// ---------------- launch ----------------
extern "C" void kernel_launch(void* const* d_in, const int* in_sizes, int n_in,
                              void* d_out, int out_size){
    const float* x    = (const float*)d_in[0];
    const float* ge   = (const float*)d_in[1];
    const float* Wq   = (const float*)d_in[2];
    const float* bq   = (const float*)d_in[3];
    const float* Wk   = (const float*)d_in[4];
    const float* bk   = (const float*)d_in[5];
    const float* Wv   = (const float*)d_in[6];
    const float* bv   = (const float*)d_in[7];
    const float* ln1g = (const float*)d_in[8];
    const float* ln1b = (const float*)d_in[9];
    const float* ln2g = (const float*)d_in[10];
    const float* ln2b = (const float*)d_in[11];
    const float* WU   = (const float*)d_in[12];
    const float* bU   = (const float*)d_in[13];
    const float* WV   = (const float*)d_in[14];
    const float* bV   = (const float*)d_in[15];
    const float* Wo   = (const float*)d_in[16];
    const float* bo   = (const float*)d_in[17];
    float* out = (float*)d_out;

    float *ph, *pq, *pk, *pv;
    uint32_t *pzh, *pzl, *puh, *pul;
    uint32_t *pWqh,*pWql,*pWkh,*pWkl,*pWvh,*pWvl,*pWUh,*pWUl,*pWVh,*pWVl;
    cudaGetSymbolAddress((void**)&ph, g_h);
    cudaGetSymbolAddress((void**)&pq, g_q);
    cudaGetSymbolAddress((void**)&pk, g_k);
    cudaGetSymbolAddress((void**)&pv, g_v);
    cudaGetSymbolAddress((void**)&pzh, g_zh);
    cudaGetSymbolAddress((void**)&pzl, g_zl);
    cudaGetSymbolAddress((void**)&puh, g_uh);
    cudaGetSymbolAddress((void**)&pul, g_ul);
    cudaGetSymbolAddress((void**)&pWqh, g_Wqh);
    cudaGetSymbolAddress((void**)&pWql, g_Wql);
    cudaGetSymbolAddress((void**)&pWkh, g_Wkh);
    cudaGetSymbolAddress((void**)&pWkl, g_Wkl);
    cudaGetSymbolAddress((void**)&pWvh, g_Wvh);
    cudaGetSymbolAddress((void**)&pWvl, g_Wvl);
    cudaGetSymbolAddress((void**)&pWUh, g_WUh);
    cudaGetSymbolAddress((void**)&pWUl, g_WUl);
    cudaGetSymbolAddress((void**)&pWVh, g_WVh);
    cudaGetSymbolAddress((void**)&pWVl, g_WVl);

    cudaFuncSetAttribute(mma_gemm<EPI_NONE,false,true,false>,
        cudaFuncAttributeMaxDynamicSharedMemorySize, SMEM_GEMM);
    cudaFuncSetAttribute(mma_gemm<EPI_GELU,false,false,true>,
        cudaFuncAttributeMaxDynamicSharedMemorySize, SMEM_GEMM);
    cudaFuncSetAttribute(mma_gemm<EPI_NONE,true,false,false>,
        cudaFuncAttributeMaxDynamicSharedMemorySize, SMEM_GEMM);

    // all weights packed in ONE launch
    packAll_kernel<<<PACK_TOTAL/256, 256>>>(Wq, Wk, Wv, WU, WV);

    embed_kernel<<<BGc, Dc>>>(x, ge);

    const size_t wqkv = (size_t)(Dc/2)*Dc;
    const size_t wu   = (size_t)(Dc/2)*FFNc;
    const size_t wv2  = (size_t)(FFNc/2)*Dc;

    for (int l=0;l<Lc;l++){
        ln_kernel<<<BGc/8, 256>>>(ph, ln1g + l*Dc, ln1b + l*Dc, pzh, pzl);
        dim3 gqkv(Dc/128, BGc/64, 3);
        mma_gemm<EPI_NONE,false,true,false><<<gqkv,128,SMEM_GEMM>>>(BGc, Dc, Dc, pzh, pzl,
            pWqh + l*wqkv, pWql + l*wqkv,
            pWkh + l*wqkv, pWkl + l*wqkv,
            pWvh + l*wqkv, pWvl + l*wqkv,
            bq + l*Dc, bk + l*Dc, bv + l*Dc,
            pq, pk, pv, 0, 0);
        scanA_kernel<<<Bc*Hc*NCc, 256>>>();
        scanB_kernel<<<Bc*Hc*8, 128>>>();
        scanC_kernel<<<Bc*Hc*NCc, 256>>>();

        ln_kernel<<<BGc/8, 256>>>(ph, ln2g + l*Dc, ln2b + l*Dc, pzh, pzl);
        dim3 gu(FFNc/128, BGc/64, 1);
        mma_gemm<EPI_GELU,false,false,true><<<gu,128,SMEM_GEMM>>>(BGc, FFNc, Dc, pzh, pzl,
            pWUh + l*wu, pWUl + l*wu, 0,0,0,0,
            bU + l*FFNc, 0, 0,
            0, 0, 0, puh, pul);
        dim3 gv(Dc/128, BGc/64, 1);
        mma_gemm<EPI_NONE,true,false,false><<<gv,128,SMEM_GEMM>>>(BGc, Dc, FFNc, puh, pul,
            pWVh + l*wv2, pWVl + l*wv2, 0,0,0,0,
            bV + l*Dc, 0, 0,
            ph, 0, 0, 0, 0);
    }

    out_kernel<<<BGc/8, 256>>>(Wo, bo, out);
}

// round 15
// speedup vs baseline: 1.8177x; 1.0264x over previous
#include <cuda_runtime.h>
#include <cuda_bf16.h>
#include <math.h>
#include <stdint.h>

#define Bc 4
#define Gc 2048
#define Dc 256
#define Hc 8
#define Lc 4
#define FFNc 1024
#define HDc 32
#define BGc (Bc*Gc)
#define NCc 32
#define Tc (Gc/NCc)   /* 64 */

// ---------------- scratch (no mallocs allowed) ----------------
__device__ float g_h[BGc*Dc];
__device__ float g_q[BGc*Dc];
__device__ float g_k[BGc*Dc];
__device__ float g_v[BGc*Dc];
__device__ float g_cKV[Bc*Hc*NCc*HDc*HDc];
__device__ float g_cK[Bc*Hc*NCc*HDc];

// packed bf16 hi/lo activations
__device__ uint32_t g_zh[BGc*Dc/2];
__device__ uint32_t g_zl[BGc*Dc/2];
__device__ uint32_t g_uh[BGc*FFNc/2];
__device__ uint32_t g_ul[BGc*FFNc/2];
// packed bf16 hi/lo weights (k2-major rows, n columns)
__device__ uint32_t g_Wqh[Lc*(Dc/2)*Dc];
__device__ uint32_t g_Wql[Lc*(Dc/2)*Dc];
__device__ uint32_t g_Wkh[Lc*(Dc/2)*Dc];
__device__ uint32_t g_Wkl[Lc*(Dc/2)*Dc];
__device__ uint32_t g_Wvh[Lc*(Dc/2)*Dc];
__device__ uint32_t g_Wvl[Lc*(Dc/2)*Dc];
__device__ uint32_t g_WUh[Lc*(Dc/2)*FFNc];
__device__ uint32_t g_WUl[Lc*(Dc/2)*FFNc];
__device__ uint32_t g_WVh[Lc*(FFNc/2)*Dc];
__device__ uint32_t g_WVl[Lc*(FFNc/2)*Dc];

// ---------------- helpers ----------------
__device__ __forceinline__ uint16_t bfb(float x){
    __nv_bfloat16 h = __float2bfloat16(x);
    return *reinterpret_cast<uint16_t*>(&h);
}
__device__ __forceinline__ float bff(uint16_t b){
    __nv_bfloat16 h = *reinterpret_cast<__nv_bfloat16*>(&b);
    return __bfloat162float(h);
}
__device__ __forceinline__ uint32_t pack2(uint16_t lo, uint16_t hi){
    return ((uint32_t)hi<<16) | (uint32_t)lo;
}
__device__ __forceinline__ void mma16816(float* c, const uint32_t* a, const uint32_t* b){
    asm volatile("mma.sync.aligned.m16n8k16.row.col.f32.bf16.bf16.f32 "
        "{%0,%1,%2,%3}, {%4,%5,%6,%7}, {%8,%9}, {%0,%1,%2,%3};\n"
        : "+f"(c[0]),"+f"(c[1]),"+f"(c[2]),"+f"(c[3])
        : "r"(a[0]),"r"(a[1]),"r"(a[2]),"r"(a[3]), "r"(b[0]),"r"(b[1]));
}
__device__ __forceinline__ void cpa16(uint32_t s, const void* g){
    asm volatile("cp.async.cg.shared.global [%0], [%1], 16;" :: "r"(s), "l"(g));
}
#define CP_COMMIT() asm volatile("cp.async.commit_group;")
#define CP_WAIT0()  asm volatile("cp.async.wait_group 0;")

// ---------------- merged weight packer: all 5 tensors in ONE launch ----------------
#define S1c  (Lc*(Dc/2)*Dc)     /* 131072 */
#define SUc  (Lc*(Dc/2)*FFNc)   /* 524288 */
#define SVc  (Lc*(FFNc/2)*Dc)   /* 524288 */
#define PACK_TOTAL (3*S1c + SUc + SVc)  /* 1441792 */

__global__ void packAll_kernel(const float* __restrict__ Wq, const float* __restrict__ Wk,
                               const float* __restrict__ Wv, const float* __restrict__ WU,
                               const float* __restrict__ WV){
    int t = blockIdx.x*256 + threadIdx.x;
    const float* W; uint32_t *Ph, *Pl; int N, r;
    if (t < 3*S1c){
        int which = t / S1c; r = t - which*S1c;
        W  = (which==0)?Wq:((which==1)?Wk:Wv);
        Ph = (which==0)?g_Wqh:((which==1)?g_Wkh:g_Wvh);
        Pl = (which==0)?g_Wql:((which==1)?g_Wkl:g_Wvl);
        N = Dc;
    } else if (t < 3*S1c + SUc){
        r = t - 3*S1c; W = WU; Ph = g_WUh; Pl = g_WUl; N = FFNc;
    } else {
        r = t - 3*S1c - SUc; W = WV; Ph = g_WVh; Pl = g_WVl; N = Dc;
    }
    int row = r / N, n = r - row*N;
    float a = W[(size_t)(2*row)*N + n];
    float b = W[(size_t)(2*row+1)*N + n];
    uint16_t ha = bfb(a), hb = bfb(b);
    Ph[(size_t)row*N + n] = pack2(ha,hb);
    Pl[(size_t)row*N + n] = pack2(bfb(a-bff(ha)), bfb(b-bff(hb)));
}

// ---------------- embed ----------------
__global__ void embed_kernel(const float* __restrict__ x, const float* __restrict__ ge){
    int row = blockIdx.x;
    int d = threadIdx.x;
    int g = row % Gc;
    float xv = x[row];
    int i = (d < Dc/2) ? d : d - Dc/2;
    float invf = expf(-((2.0f*(float)i)/(float)Dc) * 4.6051701859880914f);
    float f = xv * invf;
    float ree = (d < Dc/2) ? sinf(f) : cosf(f);
    if (xv == -10.0f) ree = 0.0f;
    g_h[(size_t)row*Dc + d] = ge[(size_t)g*Dc + d] + ree;
}

// ---------------- layernorm: warp-per-row, packed hi/lo output ----------------
__global__ void ln_kernel(const float* __restrict__ in, const float* __restrict__ gamma,
                          const float* __restrict__ beta,
                          uint32_t* __restrict__ zh, uint32_t* __restrict__ zl){
    int row  = blockIdx.x*8 + (threadIdx.x >> 5);
    int lane = threadIdx.x & 31;
    const float2* p = (const float2*)(in + (size_t)row*Dc);
    float2 v[4]; float s = 0.f;
    #pragma unroll
    for (int j=0;j<4;j++){ v[j] = p[lane + j*32]; s += v[j].x + v[j].y; }
    #pragma unroll
    for (int o=16;o;o>>=1) s += __shfl_xor_sync(0xffffffffu, s, o);
    float mu = s * (1.0f/(float)Dc);
    float vs = 0.f;
    #pragma unroll
    for (int j=0;j<4;j++){
        float dx = v[j].x-mu, dy = v[j].y-mu;
        vs += dx*dx + dy*dy;
    }
    #pragma unroll
    for (int o=16;o;o>>=1) vs += __shfl_xor_sync(0xffffffffu, vs, o);
    float r = rsqrtf(vs*(1.0f/(float)Dc) + 1e-5f);
    const float2* gg = (const float2*)gamma;
    const float2* bb = (const float2*)beta;
    #pragma unroll
    for (int j=0;j<4;j++){
        int c2 = lane + j*32;
        float2 gv = gg[c2], bv = bb[c2];
        float a = (v[j].x-mu)*r*gv.x + bv.x;
        float b = (v[j].y-mu)*r*gv.y + bv.y;
        uint16_t ha = bfb(a), hb = bfb(b);
        zh[(size_t)row*(Dc/2) + c2] = pack2(ha,hb);
        zl[(size_t)row*(Dc/2) + c2] = pack2(bfb(a-bff(ha)), bfb(b-bff(hb)));
    }
}

// ---------------- bf16 split tensor-core GEMM, 128x128 tile, 256 thr, cp.async 2-buf ----------------
#define EPI_NONE   0
#define EPI_SQUARE 1
#define EPI_GELU   2

#define ASTR32 20
#define BSTR32 136
#define AU32   (128*ASTR32)      /* 2560 */
#define BU32   (16*BSTR32)       /* 2176 */
#define BUFU32 (2*AU32 + 2*BU32) /* 9472 u32 = 37888 B */
#define SMEM_GEMM (2*BUFU32*4)   /* 75776 B */

template<int EPI, bool RES, bool QKV, bool OUTPK>
__global__ void __launch_bounds__(256,2) mma_gemm(int M, int N, int K,
        const uint32_t* __restrict__ Agh, const uint32_t* __restrict__ Agl,
        const uint32_t* W0h, const uint32_t* W0l,
        const uint32_t* W1h, const uint32_t* W1l,
        const uint32_t* W2h, const uint32_t* W2l,
        const float* b0, const float* b1, const float* b2,
        float* C0, float* C1, float* C2,
        uint32_t* Coh, uint32_t* Col){
    extern __shared__ __align__(16) uint32_t smem[];

    const int z = QKV ? blockIdx.z : 0;
    const uint32_t* Bwh = QKV ? ((z==0)?W0h:((z==1)?W1h:W2h)) : W0h;
    const uint32_t* Bwl = QKV ? ((z==0)?W0l:((z==1)?W1l:W2l)) : W0l;
    const float* bias   = QKV ? ((z==0)?b0:((z==1)?b1:b2)) : b0;
    float*       C      = QKV ? ((z==0)?C0:((z==1)?C1:C2)) : C0;

    const int Kp = K/2;
    const int tid  = threadIdx.x;
    const int row0 = blockIdx.y*128;
    const int col0 = blockIdx.x*128;
    const int w    = tid>>5;
    const int wm   = w & 3;        // 4 M-quads of 32 rows
    const int wn   = w >> 2;       // 2 N-halves of 64 cols
    const int lane = tid & 31;
    const int g    = lane >> 2;
    const int t4   = lane & 3;

    // loader indices (256 threads)
    const int ar  = tid>>1, ac = (tid&1)*8;      // A: 128 rows x 16 u32
    const int bk2 = tid>>4, bn = (tid&15)*8;     // B: 16 rows x 128 u32, one pass

    uint32_t sbase = (uint32_t)__cvta_generic_to_shared(smem);

    auto issue = [&](int bfr, int kt){
        int k0p = kt*16;
        uint32_t ah = sbase + (bfr*BUFU32)*4;
        uint32_t al = ah + AU32*4;
        uint32_t bh = al + AU32*4;
        uint32_t bl = bh + BU32*4;
        const uint32_t* gAh = Agh + (size_t)(row0+ar)*Kp + k0p + ac;
        const uint32_t* gAl = Agl + (size_t)(row0+ar)*Kp + k0p + ac;
        uint32_t sA = (ar*ASTR32 + ac)*4;
        cpa16(ah + sA,      gAh);
        cpa16(ah + sA + 16, gAh + 4);
        cpa16(al + sA,      gAl);
        cpa16(al + sA + 16, gAl + 4);
        const uint32_t* gBh = Bwh + (size_t)(k0p+bk2)*N + col0 + bn;
        const uint32_t* gBl = Bwl + (size_t)(k0p+bk2)*N + col0 + bn;
        uint32_t sB = (bk2*BSTR32 + bn)*4;
        cpa16(bh + sB,      gBh);
        cpa16(bh + sB + 16, gBh + 4);
        cpa16(bl + sB,      gBl);
        cpa16(bl + sB + 16, gBl + 4);
        CP_COMMIT();
    };

    float acc[2][8][4];
    #pragma unroll
    for (int mt=0;mt<2;mt++)
        #pragma unroll
        for (int nt=0;nt<8;nt++)
            #pragma unroll
            for (int q=0;q<4;q++) acc[mt][nt][q]=0.f;

    const int nk = K/32;
    issue(0, 0);

    for (int kt=0; kt<nk; kt++){
        const int cur = kt & 1;
        CP_WAIT0();
        __syncthreads();
        if (kt+1 < nk) issue(cur^1, kt+1);

        const uint32_t* AhS = smem + cur*BUFU32;
        const uint32_t* AlS = AhS + AU32;
        const uint32_t* BhS = AlS + AU32;
        const uint32_t* BlS = BhS + BU32;

        #pragma unroll
        for (int ks=0;ks<2;ks++){
            uint32_t afh[2][4], afl[2][4];
            #pragma unroll
            for (int mt=0;mt<2;mt++){
                int r  = wm*32 + mt*16 + g;
                int cb = ks*8 + t4;
                afh[mt][0]=AhS[r*ASTR32+cb];
                afh[mt][1]=AhS[(r+8)*ASTR32+cb];
                afh[mt][2]=AhS[r*ASTR32+cb+4];
                afh[mt][3]=AhS[(r+8)*ASTR32+cb+4];
                afl[mt][0]=AlS[r*ASTR32+cb];
                afl[mt][1]=AlS[(r+8)*ASTR32+cb];
                afl[mt][2]=AlS[r*ASTR32+cb+4];
                afl[mt][3]=AlS[(r+8)*ASTR32+cb+4];
            }
            #pragma unroll
            for (int nt=0;nt<8;nt++){
                int n  = wn*64 + nt*8 + g;
                int k2 = ks*8 + t4;
                uint32_t bhv[2], blv[2];
                bhv[0]=BhS[k2*BSTR32+n]; bhv[1]=BhS[(k2+4)*BSTR32+n];
                blv[0]=BlS[k2*BSTR32+n]; blv[1]=BlS[(k2+4)*BSTR32+n];
                // distance-2 same-accumulator spacing
                mma16816(acc[0][nt], afh[0], bhv);
                mma16816(acc[1][nt], afh[1], bhv);
                mma16816(acc[0][nt], afh[0], blv);
                mma16816(acc[1][nt], afh[1], blv);
                mma16816(acc[0][nt], afl[0], bhv);
                mma16816(acc[1][nt], afl[1], bhv);
            }
        }
        __syncthreads();
    }

    const int epi = QKV ? ((z==2) ? EPI_NONE : EPI_SQUARE) : EPI;
    #pragma unroll
    for (int mt=0;mt<2;mt++){
        #pragma unroll
        for (int nt=0;nt<8;nt++){
            int r = row0 + wm*32 + mt*16 + g;
            int n = col0 + wn*64 + nt*8 + t4*2;
            #pragma unroll
            for (int half=0; half<2; half++){
                int rr = r + half*8;
                float v0 = acc[mt][nt][half*2+0] + bias[n];
                float v1 = acc[mt][nt][half*2+1] + bias[n+1];
                if (epi == EPI_SQUARE){ v0=v0*v0; v1=v1*v1; }
                if (epi == EPI_GELU){
                    v0 = 0.5f*v0*(1.0f + erff(v0*0.70710678118654752f));
                    v1 = 0.5f*v1*(1.0f + erff(v1*0.70710678118654752f));
                }
                if (OUTPK){
                    uint16_t h0 = bfb(v0), h1 = bfb(v1);
                    Coh[(size_t)rr*(N/2) + (n>>1)] = pack2(h0,h1);
                    Col[(size_t)rr*(N/2) + (n>>1)] = pack2(bfb(v0-bff(h0)), bfb(v1-bff(h1)));
                } else {
                    size_t idx = (size_t)rr*N + n;
                    if (RES){ C[idx] += v0; C[idx+1] += v1; }
                    else    { C[idx]  = v0; C[idx+1]  = v1; }
                }
            }
        }
    }
}

// ---------------- attention scan (R7 verbatim) ----------------
__global__ void __launch_bounds__(256) scanA_kernel(){
    __shared__ float Ks[Tc][33];
    __shared__ float Vs[Tc][33];
    int bid = blockIdx.x;
    int c  = bid & (NCc-1);
    int bh = bid >> 5;
    int b  = bh >> 3;
    int hh = bh & 7;
    int tid = threadIdx.x;
    size_t base = ((size_t)(b*Gc + c*Tc))*Dc + hh*HDc;
    #pragma unroll
    for (int i=0;i<8;i++){
        int idx = tid + i*256;
        int s = idx >> 5, m = idx & 31;
        size_t gi = base + (size_t)s*Dc + m;
        Ks[s][m] = g_k[gi];
        Vs[s][m] = g_v[gi];
    }
    __syncthreads();
    int d  = tid >> 3;
    int mg = (tid & 7)*4;
    float a0=0.f,a1=0.f,a2=0.f,a3=0.f;
    #pragma unroll
    for (int s=0;s<Tc;s++){
        float vd = Vs[s][d];
        a0 += vd*Ks[s][mg+0]; a1 += vd*Ks[s][mg+1];
        a2 += vd*Ks[s][mg+2]; a3 += vd*Ks[s][mg+3];
    }
    float* o = &g_cKV[(size_t)bid*1024 + d*32 + mg];
    o[0]=a0; o[1]=a1; o[2]=a2; o[3]=a3;
    if (tid < 32){
        float ks = 0.f;
        #pragma unroll
        for (int s=0;s<Tc;s++) ks += Ks[s][tid];
        g_cK[bid*32 + tid] = ks;
    }
}

__global__ void scanB_kernel(){
    int bh  = blockIdx.x >> 3;
    int seg = blockIdx.x & 7;
    int t   = seg*128 + threadIdx.x;
    float run = 0.f;
    for (int c=0;c<NCc;c++){
        size_t idx = ((size_t)(bh*NCc + c))*1024 + t;
        float val = g_cKV[idx];
        g_cKV[idx] = run;
        run += val;
    }
    if (seg == 0 && threadIdx.x < 32){
        float run2 = 0.f;
        int m = threadIdx.x;
        for (int c=0;c<NCc;c++){
            int idx = (bh*NCc + c)*32 + m;
            float val = g_cK[idx];
            g_cK[idx] = run2;
            run2 += val;
        }
    }
}

__global__ void __launch_bounds__(256) scanC_kernel(){
    __shared__ float Qs[Tc][33];
    __shared__ float Ks[Tc][33];
    __shared__ float Vs[Tc][33];
    __shared__ float Ps[Tc][65];
    __shared__ float KVsm[32*33];
    __shared__ float kps[32];
    __shared__ float dens[Tc];
    int bid = blockIdx.x;
    int c  = bid & (NCc-1);
    int bh = bid >> 5;
    int b  = bh >> 3;
    int hh = bh & 7;
    int tid = threadIdx.x;
    size_t base = ((size_t)(b*Gc + c*Tc))*Dc + hh*HDc;
    #pragma unroll
    for (int i=0;i<8;i++){
        int idx = tid + i*256;
        int s = idx >> 5, m = idx & 31;
        size_t gi = base + (size_t)s*Dc + m;
        Qs[s][m] = g_q[gi];
        Ks[s][m] = g_k[gi];
        Vs[s][m] = g_v[gi];
    }
    #pragma unroll
    for (int i=0;i<4;i++){
        int idx = tid + i*256;
        int d = idx >> 5, m = idx & 31;
        KVsm[m*33 + d] = g_cKV[(size_t)bid*1024 + idx];
    }
    if (tid < 32) kps[tid] = g_cK[bid*32 + tid];
    __syncthreads();
    {
        int s = tid >> 2;
        int quad = tid & 3;
        float qreg[32];
        #pragma unroll
        for (int m=0;m<32;m++) qreg[m] = Qs[s][m];
        float rowsum = 0.f;
        #pragma unroll
        for (int j=0;j<16;j++){
            int t = quad + j*4;
            float dot = 0.f;
            #pragma unroll
            for (int m=0;m<32;m++) dot += qreg[m]*Ks[t][m];
            float pv = (t <= s) ? dot : 0.f;
            Ps[s][t] = pv;
            rowsum += pv;
        }
        rowsum += __shfl_xor_sync(0xffffffffu, rowsum, 1);
        rowsum += __shfl_xor_sync(0xffffffffu, rowsum, 2);
        if (quad == 0) dens[s] = rowsum;
    }
    __syncthreads();
    if (tid < Tc){
        float den = dens[tid];
        #pragma unroll
        for (int m=0;m<32;m++) den += Qs[tid][m]*kps[m];
        dens[tid] = den + 1e-16f;
    }
    __syncthreads();
    #pragma unroll
    for (int i=0;i<8;i++){
        int idx = tid + i*256;
        int s = idx >> 5, d = idx & 31;
        float num = 0.f;
        #pragma unroll
        for (int t=0;t<Tc;t++) num += Ps[s][t]*Vs[t][d];
        #pragma unroll
        for (int m=0;m<32;m++) num += Qs[s][m]*KVsm[m*33 + d];
        g_h[base + (size_t)s*Dc + d] += num / dens[s];
    }
}

// ---------------- head ----------------
__global__ void out_kernel(const float* __restrict__ Wo, const float* __restrict__ bo,
                           float* __restrict__ out){
    int row  = blockIdx.x*8 + (threadIdx.x >> 5);
    int lane = threadIdx.x & 31;
    float s = 0.f;
    #pragma unroll
    for (int j=0;j<8;j++){
        int d = lane + j*32;
        s += g_h[(size_t)row*Dc + d] * Wo[d];
    }
    #pragma unroll
    for (int o=16;o;o>>=1) s += __shfl_xor_sync(0xffffffffu, s, o);
    if (lane == 0) out[row] = s + bo[0];
}

// ---------------- launch ----------------
extern "C" void kernel_launch(void* const* d_in, const int* in_sizes, int n_in,
                              void* d_out, int out_size){
    const float* x    = (const float*)d_in[0];
    const float* ge   = (const float*)d_in[1];
    const float* Wq   = (const float*)d_in[2];
    const float* bq   = (const float*)d_in[3];
    const float* Wk   = (const float*)d_in[4];
    const float* bk   = (const float*)d_in[5];
    const float* Wv   = (const float*)d_in[6];
    const float* bv   = (const float*)d_in[7];
    const float* ln1g = (const float*)d_in[8];
    const float* ln1b = (const float*)d_in[9];
    const float* ln2g = (const float*)d_in[10];
    const float* ln2b = (const float*)d_in[11];
    const float* WU   = (const float*)d_in[12];
    const float* bU   = (const float*)d_in[13];
    const float* WV   = (const float*)d_in[14];
    const float* bV   = (const float*)d_in[15];
    const float* Wo   = (const float*)d_in[16];
    const float* bo   = (const float*)d_in[17];
    float* out = (float*)d_out;

    float *ph, *pq, *pk, *pv;
    uint32_t *pzh, *pzl, *puh, *pul;
    uint32_t *pWqh,*pWql,*pWkh,*pWkl,*pWvh,*pWvl,*pWUh,*pWUl,*pWVh,*pWVl;
    cudaGetSymbolAddress((void**)&ph, g_h);
    cudaGetSymbolAddress((void**)&pq, g_q);
    cudaGetSymbolAddress((void**)&pk, g_k);
    cudaGetSymbolAddress((void**)&pv, g_v);
    cudaGetSymbolAddress((void**)&pzh, g_zh);
    cudaGetSymbolAddress((void**)&pzl, g_zl);
    cudaGetSymbolAddress((void**)&puh, g_uh);
    cudaGetSymbolAddress((void**)&pul, g_ul);
    cudaGetSymbolAddress((void**)&pWqh, g_Wqh);
    cudaGetSymbolAddress((void**)&pWql, g_Wql);
    cudaGetSymbolAddress((void**)&pWkh, g_Wkh);
    cudaGetSymbolAddress((void**)&pWkl, g_Wkl);
    cudaGetSymbolAddress((void**)&pWvh, g_Wvh);
    cudaGetSymbolAddress((void**)&pWvl, g_Wvl);
    cudaGetSymbolAddress((void**)&pWUh, g_WUh);
    cudaGetSymbolAddress((void**)&pWUl, g_WUl);
    cudaGetSymbolAddress((void**)&pWVh, g_WVh);
    cudaGetSymbolAddress((void**)&pWVl, g_WVl);

    cudaFuncSetAttribute(mma_gemm<EPI_NONE,false,true,false>,
        cudaFuncAttributeMaxDynamicSharedMemorySize, SMEM_GEMM);
    cudaFuncSetAttribute(mma_gemm<EPI_GELU,false,false,true>,
        cudaFuncAttributeMaxDynamicSharedMemorySize, SMEM_GEMM);
    cudaFuncSetAttribute(mma_gemm<EPI_NONE,true,false,false>,
        cudaFuncAttributeMaxDynamicSharedMemorySize, SMEM_GEMM);

    packAll_kernel<<<PACK_TOTAL/256, 256>>>(Wq, Wk, Wv, WU, WV);

    embed_kernel<<<BGc, Dc>>>(x, ge);

    const size_t wqkv = (size_t)(Dc/2)*Dc;
    const size_t wu   = (size_t)(Dc/2)*FFNc;
    const size_t wv2  = (size_t)(FFNc/2)*Dc;

    for (int l=0;l<Lc;l++){
        ln_kernel<<<BGc/8, 256>>>(ph, ln1g + l*Dc, ln1b + l*Dc, pzh, pzl);
        dim3 gqkv(Dc/128, BGc/128, 3);
        mma_gemm<EPI_NONE,false,true,false><<<gqkv,256,SMEM_GEMM>>>(BGc, Dc, Dc, pzh, pzl,
            pWqh + l*wqkv, pWql + l*wqkv,
            pWkh + l*wqkv, pWkl + l*wqkv,
            pWvh + l*wqkv, pWvl + l*wqkv,
            bq + l*Dc, bk + l*Dc, bv + l*Dc,
            pq, pk, pv, 0, 0);
        scanA_kernel<<<Bc*Hc*NCc, 256>>>();
        scanB_kernel<<<Bc*Hc*8, 128>>>();
        scanC_kernel<<<Bc*Hc*NCc, 256>>>();

        ln_kernel<<<BGc/8, 256>>>(ph, ln2g + l*Dc, ln2b + l*Dc, pzh, pzl);
        dim3 gu(FFNc/128, BGc/128, 1);
        mma_gemm<EPI_GELU,false,false,true><<<gu,256,SMEM_GEMM>>>(BGc, FFNc, Dc, pzh, pzl,
            pWUh + l*wu, pWUl + l*wu, 0,0,0,0,
            bU + l*FFNc, 0, 0,
            0, 0, 0, puh, pul);
        dim3 gv(Dc/128, BGc/128, 1);
        mma_gemm<EPI_NONE,true,false,false><<<gv,256,SMEM_GEMM>>>(BGc, Dc, FFNc, puh, pul,
            pWVh + l*wv2, pWVl + l*wv2, 0,0,0,0,
            bV + l*Dc, 0, 0,
            ph, 0, 0, 0, 0);
    }

    out_kernel<<<BGc/8, 256>>>(Wo, bo, out);
}

// round 16
// speedup vs baseline: 1.8257x; 1.0044x over previous
#include <cuda_runtime.h>
#include <cuda_bf16.h>
#include <math.h>
#include <stdint.h>

#define Bc 4
#define Gc 2048
#define Dc 256
#define Hc 8
#define Lc 4
#define FFNc 1024
#define HDc 32
#define BGc (Bc*Gc)
#define NCc 32
#define Tc (Gc/NCc)   /* 64 */

// ---------------- scratch (no mallocs allowed) ----------------
__device__ float g_h[BGc*Dc];
__device__ float g_q[BGc*Dc];
__device__ float g_k[BGc*Dc];
__device__ float g_v[BGc*Dc];
__device__ float g_p[2*BGc*Dc];
__device__ float g_cKV[Bc*Hc*NCc*HDc*HDc];
__device__ float g_cK[Bc*Hc*NCc*HDc];

// packed bf16 hi/lo activations
__device__ uint32_t g_zh[BGc*Dc/2];
__device__ uint32_t g_zl[BGc*Dc/2];
__device__ uint32_t g_uh[BGc*FFNc/2];
__device__ uint32_t g_ul[BGc*FFNc/2];
// packed bf16 hi/lo weights (k2-major rows, n columns)
__device__ uint32_t g_Wqh[Lc*(Dc/2)*Dc];
__device__ uint32_t g_Wql[Lc*(Dc/2)*Dc];
__device__ uint32_t g_Wkh[Lc*(Dc/2)*Dc];
__device__ uint32_t g_Wkl[Lc*(Dc/2)*Dc];
__device__ uint32_t g_Wvh[Lc*(Dc/2)*Dc];
__device__ uint32_t g_Wvl[Lc*(Dc/2)*Dc];
__device__ uint32_t g_WUh[Lc*(Dc/2)*FFNc];
__device__ uint32_t g_WUl[Lc*(Dc/2)*FFNc];
__device__ uint32_t g_WVh[Lc*(FFNc/2)*Dc];
__device__ uint32_t g_WVl[Lc*(FFNc/2)*Dc];

// ---------------- helpers ----------------
__device__ __forceinline__ uint16_t bfb(float x){
    __nv_bfloat16 h = __float2bfloat16(x);
    return *reinterpret_cast<uint16_t*>(&h);
}
__device__ __forceinline__ float bff(uint16_t b){
    __nv_bfloat16 h = *reinterpret_cast<__nv_bfloat16*>(&b);
    return __bfloat162float(h);
}
__device__ __forceinline__ uint32_t pack2(uint16_t lo, uint16_t hi){
    return ((uint32_t)hi<<16) | (uint32_t)lo;
}
__device__ __forceinline__ void mma16816(float* c, const uint32_t* a, const uint32_t* b){
    asm volatile("mma.sync.aligned.m16n8k16.row.col.f32.bf16.bf16.f32 "
        "{%0,%1,%2,%3}, {%4,%5,%6,%7}, {%8,%9}, {%0,%1,%2,%3};\n"
        : "+f"(c[0]),"+f"(c[1]),"+f"(c[2]),"+f"(c[3])
        : "r"(a[0]),"r"(a[1]),"r"(a[2]),"r"(a[3]), "r"(b[0]),"r"(b[1]));
}
__device__ __forceinline__ void cpa16(uint32_t s, const void* g){
    asm volatile("cp.async.cg.shared.global [%0], [%1], 16;" :: "r"(s), "l"(g));
}
#define CP_COMMIT() asm volatile("cp.async.commit_group;")
#define CP_WAIT0()  asm volatile("cp.async.wait_group 0;")

// ---------------- merged weight packer ----------------
#define S1c  (Lc*(Dc/2)*Dc)
#define SUc  (Lc*(Dc/2)*FFNc)
#define SVc  (Lc*(FFNc/2)*Dc)
#define PACK_TOTAL (3*S1c + SUc + SVc)

__global__ void packAll_kernel(const float* __restrict__ Wq, const float* __restrict__ Wk,
                               const float* __restrict__ Wv, const float* __restrict__ WU,
                               const float* __restrict__ WV){
    int t = blockIdx.x*256 + threadIdx.x;
    const float* W; uint32_t *Ph, *Pl; int N, r;
    if (t < 3*S1c){
        int which = t / S1c; r = t - which*S1c;
        W  = (which==0)?Wq:((which==1)?Wk:Wv);
        Ph = (which==0)?g_Wqh:((which==1)?g_Wkh:g_Wvh);
        Pl = (which==0)?g_Wql:((which==1)?g_Wkl:g_Wvl);
        N = Dc;
    } else if (t < 3*S1c + SUc){
        r = t - 3*S1c; W = WU; Ph = g_WUh; Pl = g_WUl; N = FFNc;
    } else {
        r = t - 3*S1c - SUc; W = WV; Ph = g_WVh; Pl = g_WVl; N = Dc;
    }
    int row = r / N, n = r - row*N;
    float a = W[(size_t)(2*row)*N + n];
    float b = W[(size_t)(2*row+1)*N + n];
    uint16_t ha = bfb(a), hb = bfb(b);
    Ph[(size_t)row*N + n] = pack2(ha,hb);
    Pl[(size_t)row*N + n] = pack2(bfb(a-bff(ha)), bfb(b-bff(hb)));
}

// ---------------- embed ----------------
__global__ void embed_kernel(const float* __restrict__ x, const float* __restrict__ ge){
    int row = blockIdx.x;
    int d = threadIdx.x;
    int g = row % Gc;
    float xv = x[row];
    int i = (d < Dc/2) ? d : d - Dc/2;
    float invf = expf(-((2.0f*(float)i)/(float)Dc) * 4.6051701859880914f);
    float f = xv * invf;
    float ree = (d < Dc/2) ? sinf(f) : cosf(f);
    if (xv == -10.0f) ree = 0.0f;
    g_h[(size_t)row*Dc + d] = ge[(size_t)g*Dc + d] + ree;
}

// ---------------- layernorm ----------------
__global__ void ln_kernel(const float* __restrict__ in, const float* __restrict__ gamma,
                          const float* __restrict__ beta,
                          uint32_t* __restrict__ zh, uint32_t* __restrict__ zl){
    int row  = blockIdx.x*8 + (threadIdx.x >> 5);
    int lane = threadIdx.x & 31;
    const float2* p = (const float2*)(in + (size_t)row*Dc);
    float2 v[4]; float s = 0.f;
    #pragma unroll
    for (int j=0;j<4;j++){ v[j] = p[lane + j*32]; s += v[j].x + v[j].y; }
    #pragma unroll
    for (int o=16;o;o>>=1) s += __shfl_xor_sync(0xffffffffu, s, o);
    float mu = s * (1.0f/(float)Dc);
    float vs = 0.f;
    #pragma unroll
    for (int j=0;j<4;j++){
        float dx = v[j].x-mu, dy = v[j].y-mu;
        vs += dx*dx + dy*dy;
    }
    #pragma unroll
    for (int o=16;o;o>>=1) vs += __shfl_xor_sync(0xffffffffu, vs, o);
    float r = rsqrtf(vs*(1.0f/(float)Dc) + 1e-5f);
    const float2* gg = (const float2*)gamma;
    const float2* bb = (const float2*)beta;
    #pragma unroll
    for (int j=0;j<4;j++){
        int c2 = lane + j*32;
        float2 gv = gg[c2], bv = bb[c2];
        float a = (v[j].x-mu)*r*gv.x + bv.x;
        float b = (v[j].y-mu)*r*gv.y + bv.y;
        uint16_t ha = bfb(a), hb = bfb(b);
        zh[(size_t)row*(Dc/2) + c2] = pack2(ha,hb);
        zl[(size_t)row*(Dc/2) + c2] = pack2(bfb(a-bff(ha)), bfb(b-bff(hb)));
    }
}

// ---------------- bf16 split GEMM, 128x128 tile, 256 thr, cp.async 2-buf ----------------
#define EPI_NONE   0
#define EPI_SQUARE 1
#define EPI_GELU   2

#define ASTR32 20
#define BSTR32 136
#define AU32   (128*ASTR32)
#define BU32   (16*BSTR32)
#define BUFU32 (2*AU32 + 2*BU32)
#define SMEM_GEMM (2*BUFU32*4)

template<int EPI, bool RES, bool QKV, bool OUTPK, int SPLITK>
__global__ void __launch_bounds__(256,2) mma_gemm(int M, int N, int K,
        const uint32_t* __restrict__ Agh, const uint32_t* __restrict__ Agl,
        const uint32_t* W0h, const uint32_t* W0l,
        const uint32_t* W1h, const uint32_t* W1l,
        const uint32_t* W2h, const uint32_t* W2l,
        const float* b0, const float* b1, const float* b2,
        float* C0, float* C1, float* C2,
        uint32_t* Coh, uint32_t* Col){
    extern __shared__ __align__(16) uint32_t smem[];

    const int z = (QKV || SPLITK>1) ? blockIdx.z : 0;
    const uint32_t* Bwh = QKV ? ((z==0)?W0h:((z==1)?W1h:W2h)) : W0h;
    const uint32_t* Bwl = QKV ? ((z==0)?W0l:((z==1)?W1l:W2l)) : W0l;
    const float* bias   = QKV ? ((z==0)?b0:((z==1)?b1:b2)) : b0;
    float*       C      = QKV ? ((z==0)?C0:((z==1)?C1:C2)) : C0;

    const int Kp = K/2;
    const int Keff = K/SPLITK;
    if (SPLITK > 1){
        int kbegp = (z*Keff)/2;
        Agh += kbegp; Agl += kbegp;
        Bwh += (size_t)kbegp*N; Bwl += (size_t)kbegp*N;
        C   += (size_t)z*M*N;
    }

    const int tid  = threadIdx.x;
    const int row0 = blockIdx.y*128;
    const int col0 = blockIdx.x*128;
    const int w    = tid>>5;
    const int wm   = w & 3;
    const int wn   = w >> 2;
    const int lane = tid & 31;
    const int g    = lane >> 2;
    const int t4   = lane & 3;

    const int ar  = tid>>1, ac = (tid&1)*8;
    const int bk2 = tid>>4, bn = (tid&15)*8;

    uint32_t sbase = (uint32_t)__cvta_generic_to_shared(smem);

    auto issue = [&](int bfr, int kt){
        int k0p = kt*16;
        uint32_t ah = sbase + (bfr*BUFU32)*4;
        uint32_t al = ah + AU32*4;
        uint32_t bh = al + AU32*4;
        uint32_t bl = bh + BU32*4;
        const uint32_t* gAh = Agh + (size_t)(row0+ar)*Kp + k0p + ac;
        const uint32_t* gAl = Agl + (size_t)(row0+ar)*Kp + k0p + ac;
        uint32_t sA = (ar*ASTR32 + ac)*4;
        cpa16(ah + sA,      gAh);
        cpa16(ah + sA + 16, gAh + 4);
        cpa16(al + sA,      gAl);
        cpa16(al + sA + 16, gAl + 4);
        const uint32_t* gBh = Bwh + (size_t)(k0p+bk2)*N + col0 + bn;
        const uint32_t* gBl = Bwl + (size_t)(k0p+bk2)*N + col0 + bn;
        uint32_t sB = (bk2*BSTR32 + bn)*4;
        cpa16(bh + sB,      gBh);
        cpa16(bh + sB + 16, gBh + 4);
        cpa16(bl + sB,      gBl);
        cpa16(bl + sB + 16, gBl + 4);
        CP_COMMIT();
    };

    float acc[2][8][4];
    #pragma unroll
    for (int mt=0;mt<2;mt++)
        #pragma unroll
        for (int nt=0;nt<8;nt++)
            #pragma unroll
            for (int q=0;q<4;q++) acc[mt][nt][q]=0.f;

    const int nk = Keff/32;
    issue(0, 0);

    for (int kt=0; kt<nk; kt++){
        const int cur = kt & 1;
        CP_WAIT0();
        __syncthreads();
        if (kt+1 < nk) issue(cur^1, kt+1);

        const uint32_t* AhS = smem + cur*BUFU32;
        const uint32_t* AlS = AhS + AU32;
        const uint32_t* BhS = AlS + AU32;
        const uint32_t* BlS = BhS + BU32;

        #pragma unroll
        for (int ks=0;ks<2;ks++){
            uint32_t afh[2][4], afl[2][4];
            #pragma unroll
            for (int mt=0;mt<2;mt++){
                int r  = wm*32 + mt*16 + g;
                int cb = ks*8 + t4;
                afh[mt][0]=AhS[r*ASTR32+cb];
                afh[mt][1]=AhS[(r+8)*ASTR32+cb];
                afh[mt][2]=AhS[r*ASTR32+cb+4];
                afh[mt][3]=AhS[(r+8)*ASTR32+cb+4];
                afl[mt][0]=AlS[r*ASTR32+cb];
                afl[mt][1]=AlS[(r+8)*ASTR32+cb];
                afl[mt][2]=AlS[r*ASTR32+cb+4];
                afl[mt][3]=AlS[(r+8)*ASTR32+cb+4];
            }
            #pragma unroll
            for (int nt=0;nt<8;nt++){
                int n  = wn*64 + nt*8 + g;
                int k2 = ks*8 + t4;
                uint32_t bhv[2], blv[2];
                bhv[0]=BhS[k2*BSTR32+n]; bhv[1]=BhS[(k2+4)*BSTR32+n];
                blv[0]=BlS[k2*BSTR32+n]; blv[1]=BlS[(k2+4)*BSTR32+n];
                mma16816(acc[0][nt], afh[0], bhv);
                mma16816(acc[1][nt], afh[1], bhv);
                mma16816(acc[0][nt], afh[0], blv);
                mma16816(acc[1][nt], afh[1], blv);
                mma16816(acc[0][nt], afl[0], bhv);
                mma16816(acc[1][nt], afl[1], bhv);
            }
        }
        __syncthreads();
    }

    const int epi = QKV ? ((z==2) ? EPI_NONE : EPI_SQUARE) : EPI;
    #pragma unroll
    for (int mt=0;mt<2;mt++){
        #pragma unroll
        for (int nt=0;nt<8;nt++){
            int r = row0 + wm*32 + mt*16 + g;
            int n = col0 + wn*64 + nt*8 + t4*2;
            #pragma unroll
            for (int half=0; half<2; half++){
                int rr = r + half*8;
                float v0 = acc[mt][nt][half*2+0];
                float v1 = acc[mt][nt][half*2+1];
                if (SPLITK == 1){ v0 += bias[n]; v1 += bias[n+1]; }
                if (epi == EPI_SQUARE){ v0=v0*v0; v1=v1*v1; }
                if (epi == EPI_GELU){
                    v0 = 0.5f*v0*(1.0f + erff(v0*0.70710678118654752f));
                    v1 = 0.5f*v1*(1.0f + erff(v1*0.70710678118654752f));
                }
                if (OUTPK){
                    uint16_t h0 = bfb(v0), h1 = bfb(v1);
                    Coh[(size_t)rr*(N/2) + (n>>1)] = pack2(h0,h1);
                    Col[(size_t)rr*(N/2) + (n>>1)] = pack2(bfb(v0-bff(h0)), bfb(v1-bff(h1)));
                } else {
                    size_t idx = (size_t)rr*N + n;
                    if (SPLITK > 1){ C[idx] = v0; C[idx+1] = v1; }
                    else if (RES)  { C[idx] += v0; C[idx+1] += v1; }
                    else           { C[idx]  = v0; C[idx+1]  = v1; }
                }
            }
        }
    }
}

// ---------------- FFN2 split-K reduce: h += p0 + p1 + bias ----------------
__global__ void ffn2_reduce(const float* __restrict__ bias){
    int idx = blockIdx.x*256 + threadIdx.x;
    int n = idx & (Dc-1);
    g_h[idx] += g_p[idx] + g_p[(size_t)BGc*Dc + idx] + bias[n];
}

// ---------------- attention scan (R7 verbatim) ----------------
__global__ void __launch_bounds__(256) scanA_kernel(){
    __shared__ float Ks[Tc][33];
    __shared__ float Vs[Tc][33];
    int bid = blockIdx.x;
    int c  = bid & (NCc-1);
    int bh = bid >> 5;
    int b  = bh >> 3;
    int hh = bh & 7;
    int tid = threadIdx.x;
    size_t base = ((size_t)(b*Gc + c*Tc))*Dc + hh*HDc;
    #pragma unroll
    for (int i=0;i<8;i++){
        int idx = tid + i*256;
        int s = idx >> 5, m = idx & 31;
        size_t gi = base + (size_t)s*Dc + m;
        Ks[s][m] = g_k[gi];
        Vs[s][m] = g_v[gi];
    }
    __syncthreads();
    int d  = tid >> 3;
    int mg = (tid & 7)*4;
    float a0=0.f,a1=0.f,a2=0.f,a3=0.f;
    #pragma unroll
    for (int s=0;s<Tc;s++){
        float vd = Vs[s][d];
        a0 += vd*Ks[s][mg+0]; a1 += vd*Ks[s][mg+1];
        a2 += vd*Ks[s][mg+2]; a3 += vd*Ks[s][mg+3];
    }
    float* o = &g_cKV[(size_t)bid*1024 + d*32 + mg];
    o[0]=a0; o[1]=a1; o[2]=a2; o[3]=a3;
    if (tid < 32){
        float ks = 0.f;
        #pragma unroll
        for (int s=0;s<Tc;s++) ks += Ks[s][tid];
        g_cK[bid*32 + tid] = ks;
    }
}

__global__ void scanB_kernel(){
    int bh  = blockIdx.x >> 3;
    int seg = blockIdx.x & 7;
    int t   = seg*128 + threadIdx.x;
    float run = 0.f;
    for (int c=0;c<NCc;c++){
        size_t idx = ((size_t)(bh*NCc + c))*1024 + t;
        float val = g_cKV[idx];
        g_cKV[idx] = run;
        run += val;
    }
    if (seg == 0 && threadIdx.x < 32){
        float run2 = 0.f;
        int m = threadIdx.x;
        for (int c=0;c<NCc;c++){
            int idx = (bh*NCc + c)*32 + m;
            float val = g_cK[idx];
            g_cK[idx] = run2;
            run2 += val;
        }
    }
}

__global__ void __launch_bounds__(256) scanC_kernel(){
    __shared__ float Qs[Tc][33];
    __shared__ float Ks[Tc][33];
    __shared__ float Vs[Tc][33];
    __shared__ float Ps[Tc][65];
    __shared__ float KVsm[32*33];
    __shared__ float kps[32];
    __shared__ float dens[Tc];
    int bid = blockIdx.x;
    int c  = bid & (NCc-1);
    int bh = bid >> 5;
    int b  = bh >> 3;
    int hh = bh & 7;
    int tid = threadIdx.x;
    size_t base = ((size_t)(b*Gc + c*Tc))*Dc + hh*HDc;
    #pragma unroll
    for (int i=0;i<8;i++){
        int idx = tid + i*256;
        int s = idx >> 5, m = idx & 31;
        size_t gi = base + (size_t)s*Dc + m;
        Qs[s][m] = g_q[gi];
        Ks[s][m] = g_k[gi];
        Vs[s][m] = g_v[gi];
    }
    #pragma unroll
    for (int i=0;i<4;i++){
        int idx = tid + i*256;
        int d = idx >> 5, m = idx & 31;
        KVsm[m*33 + d] = g_cKV[(size_t)bid*1024 + idx];
    }
    if (tid < 32) kps[tid] = g_cK[bid*32 + tid];
    __syncthreads();
    {
        int s = tid >> 2;
        int quad = tid & 3;
        float qreg[32];
        #pragma unroll
        for (int m=0;m<32;m++) qreg[m] = Qs[s][m];
        float rowsum = 0.f;
        #pragma unroll
        for (int j=0;j<16;j++){
            int t = quad + j*4;
            float dot = 0.f;
            #pragma unroll
            for (int m=0;m<32;m++) dot += qreg[m]*Ks[t][m];
            float pv = (t <= s) ? dot : 0.f;
            Ps[s][t] = pv;
            rowsum += pv;
        }
        rowsum += __shfl_xor_sync(0xffffffffu, rowsum, 1);
        rowsum += __shfl_xor_sync(0xffffffffu, rowsum, 2);
        if (quad == 0) dens[s] = rowsum;
    }
    __syncthreads();
    if (tid < Tc){
        float den = dens[tid];
        #pragma unroll
        for (int m=0;m<32;m++) den += Qs[tid][m]*kps[m];
        dens[tid] = den + 1e-16f;
    }
    __syncthreads();
    #pragma unroll
    for (int i=0;i<8;i++){
        int idx = tid + i*256;
        int s = idx >> 5, d = idx & 31;
        float num = 0.f;
        #pragma unroll
        for (int t=0;t<Tc;t++) num += Ps[s][t]*Vs[t][d];
        #pragma unroll
        for (int m=0;m<32;m++) num += Qs[s][m]*KVsm[m*33 + d];
        g_h[base + (size_t)s*Dc + d] += num / dens[s];
    }
}

// ---------------- head ----------------
__global__ void out_kernel(const float* __restrict__ Wo, const float* __restrict__ bo,
                           float* __restrict__ out){
    int row  = blockIdx.x*8 + (threadIdx.x >> 5);
    int lane = threadIdx.x & 31;
    float s = 0.f;
    #pragma unroll
    for (int j=0;j<8;j++){
        int d = lane + j*32;
        s += g_h[(size_t)row*Dc + d] * Wo[d];
    }
    #pragma unroll
    for (int o=16;o;o>>=1) s += __shfl_xor_sync(0xffffffffu, s, o);
    if (lane == 0) out[row] = s + bo[0];
}

// ---------------- launch ----------------
extern "C" void kernel_launch(void* const* d_in, const int* in_sizes, int n_in,
                              void* d_out, int out_size){
    const float* x    = (const float*)d_in[0];
    const float* ge   = (const float*)d_in[1];
    const float* Wq   = (const float*)d_in[2];
    const float* bq   = (const float*)d_in[3];
    const float* Wk   = (const float*)d_in[4];
    const float* bk   = (const float*)d_in[5];
    const float* Wv   = (const float*)d_in[6];
    const float* bv   = (const float*)d_in[7];
    const float* ln1g = (const float*)d_in[8];
    const float* ln1b = (const float*)d_in[9];
    const float* ln2g = (const float*)d_in[10];
    const float* ln2b = (const float*)d_in[11];
    const float* WU   = (const float*)d_in[12];
    const float* bU   = (const float*)d_in[13];
    const float* WV   = (const float*)d_in[14];
    const float* bV   = (const float*)d_in[15];
    const float* Wo   = (const float*)d_in[16];
    const float* bo   = (const float*)d_in[17];
    float* out = (float*)d_out;

    float *ph, *pq, *pk, *pv, *pp;
    uint32_t *pzh, *pzl, *puh, *pul;
    uint32_t *pWqh,*pWql,*pWkh,*pWkl,*pWvh,*pWvl,*pWUh,*pWUl,*pWVh,*pWVl;
    cudaGetSymbolAddress((void**)&ph, g_h);
    cudaGetSymbolAddress((void**)&pq, g_q);
    cudaGetSymbolAddress((void**)&pk, g_k);
    cudaGetSymbolAddress((void**)&pv, g_v);
    cudaGetSymbolAddress((void**)&pp, g_p);
    cudaGetSymbolAddress((void**)&pzh, g_zh);
    cudaGetSymbolAddress((void**)&pzl, g_zl);
    cudaGetSymbolAddress((void**)&puh, g_uh);
    cudaGetSymbolAddress((void**)&pul, g_ul);
    cudaGetSymbolAddress((void**)&pWqh, g_Wqh);
    cudaGetSymbolAddress((void**)&pWql, g_Wql);
    cudaGetSymbolAddress((void**)&pWkh, g_Wkh);
    cudaGetSymbolAddress((void**)&pWkl, g_Wkl);
    cudaGetSymbolAddress((void**)&pWvh, g_Wvh);
    cudaGetSymbolAddress((void**)&pWvl, g_Wvl);
    cudaGetSymbolAddress((void**)&pWUh, g_WUh);
    cudaGetSymbolAddress((void**)&pWUl, g_WUl);
    cudaGetSymbolAddress((void**)&pWVh, g_WVh);
    cudaGetSymbolAddress((void**)&pWVl, g_WVl);

    cudaFuncSetAttribute(mma_gemm<EPI_NONE,false,true,false,1>,
        cudaFuncAttributeMaxDynamicSharedMemorySize, SMEM_GEMM);
    cudaFuncSetAttribute(mma_gemm<EPI_GELU,false,false,true,1>,
        cudaFuncAttributeMaxDynamicSharedMemorySize, SMEM_GEMM);
    cudaFuncSetAttribute(mma_gemm<EPI_NONE,false,false,false,2>,
        cudaFuncAttributeMaxDynamicSharedMemorySize, SMEM_GEMM);

    packAll_kernel<<<PACK_TOTAL/256, 256>>>(Wq, Wk, Wv, WU, WV);

    embed_kernel<<<BGc, Dc>>>(x, ge);

    const size_t wqkv = (size_t)(Dc/2)*Dc;
    const size_t wu   = (size_t)(Dc/2)*FFNc;
    const size_t wv2  = (size_t)(FFNc/2)*Dc;

    for (int l=0;l<Lc;l++){
        ln_kernel<<<BGc/8, 256>>>(ph, ln1g + l*Dc, ln1b + l*Dc, pzh, pzl);
        dim3 gqkv(Dc/128, BGc/128, 3);
        mma_gemm<EPI_NONE,false,true,false,1><<<gqkv,256,SMEM_GEMM>>>(BGc, Dc, Dc, pzh, pzl,
            pWqh + l*wqkv, pWql + l*wqkv,
            pWkh + l*wqkv, pWkl + l*wqkv,
            pWvh + l*wqkv, pWvl + l*wqkv,
            bq + l*Dc, bk + l*Dc, bv + l*Dc,
            pq, pk, pv, 0, 0);
        scanA_kernel<<<Bc*Hc*NCc, 256>>>();
        scanB_kernel<<<Bc*Hc*8, 128>>>();
        scanC_kernel<<<Bc*Hc*NCc, 256>>>();

        ln_kernel<<<BGc/8, 256>>>(ph, ln2g + l*Dc, ln2b + l*Dc, pzh, pzl);
        dim3 gu(FFNc/128, BGc/128, 1);
        mma_gemm<EPI_GELU,false,false,true,1><<<gu,256,SMEM_GEMM>>>(BGc, FFNc, Dc, pzh, pzl,
            pWUh + l*wu, pWUl + l*wu, 0,0,0,0,
            bU + l*FFNc, 0, 0,
            0, 0, 0, puh, pul);
        dim3 gv(Dc/128, BGc/128, 2);
        mma_gemm<EPI_NONE,false,false,false,2><<<gv,256,SMEM_GEMM>>>(BGc, Dc, FFNc, puh, pul,
            pWVh + l*wv2, pWVl + l*wv2, 0,0,0,0,
            bV + l*Dc, 0, 0,
            pp, 0, 0, 0, 0);
        ffn2_reduce<<<BGc*Dc/256, 256>>>(bV + l*Dc);
    }

    out_kernel<<<BGc/8, 256>>>(Wo, bo, out);
}